// round 9
// baseline (speedup 1.0000x reference)
#include <cuda_runtime.h>
#include <cuda_bf16.h>
#include <math.h>

#define BN_EPS 1e-5f

// ================= scratch =================
__device__ float g_m1[67108864];   // conv1 out, channels-last [1024][8][16][16][32]
__device__ float g_m2[16777216];   // conv2 out, channels-last [1024][256][64]
__device__ float g_m3[4194304];    // conv3 out, channels-last [1024][32][128]
__device__ float g_wT2[55296];     // [tap27][c32][o64]
__device__ float g_shift2[64];
__device__ float g_wT3[221184];    // [tap27][c64][o128]
__device__ float g_shift3[128];
__device__ float g_gw[4096];       // [1024][4]
// bf16 split operands
__device__ __nv_bfloat16 g_xh[1310720],  g_xl[1310720];    // x [1024][1280]
__device__ __nv_bfloat16 g_w1h[52428800], g_w1l[52428800]; // W1^T [40960][1280]
__device__ __nv_bfloat16 g_w2h[26214400], g_w2l[26214400]; // W2^T [1280][20480]
__device__ __nv_bfloat16 g_hh[20971520],  g_hl[20971520];  // hid [1024][20480] (UNscaled)
__device__ float g_part[5242880];  // [4 experts][1024][1280] per-expert outputs

// ================= helpers =================
__device__ __forceinline__ unsigned smem_u32(const void* ptr) {
    unsigned a;
    asm("{ .reg .u64 t; cvta.to.shared.u64 t, %1; cvt.u32.u64 %0, t; }" : "=r"(a) : "l"(ptr));
    return a;
}
#define CP_ASYNC16(dst, src) \
    asm volatile("cp.async.cg.shared.global [%0], [%1], 16;" :: "r"(dst), "l"(src))
#define CP_COMMIT() asm volatile("cp.async.commit_group;" ::: "memory")
#define CP_WAIT2()  asm volatile("cp.async.wait_group 2;" ::: "memory")

__device__ __forceinline__ void ldsm4(unsigned* r, unsigned addr) {
    asm volatile("ldmatrix.sync.aligned.m8n8.x4.shared.b16 {%0,%1,%2,%3}, [%4];"
                 : "=r"(r[0]), "=r"(r[1]), "=r"(r[2]), "=r"(r[3]) : "r"(addr));
}
#define MMA16816(c, a, b0v, b1v) \
    asm volatile("mma.sync.aligned.m16n8k16.row.col.f32.bf16.bf16.f32 " \
        "{%0,%1,%2,%3}, {%4,%5,%6,%7}, {%8,%9}, {%0,%1,%2,%3};" \
        : "+f"((c)[0]), "+f"((c)[1]), "+f"((c)[2]), "+f"((c)[3]) \
        : "r"((a)[0]), "r"((a)[1]), "r"((a)[2]), "r"((a)[3]), "r"(b0v), "r"(b1v))

// ================= prep: conv weights + BN fold -> [tap][c][o] =================
template<int WHICH>
__global__ void prep_kernel(const float* __restrict__ w, const float* __restrict__ bias,
                            const float* __restrict__ bng, const float* __restrict__ bnb,
                            const float* __restrict__ bnm, const float* __restrict__ bnv) {
    constexpr int CIN  = (WHICH == 2) ? 32 : 64;
    constexpr int COUT = (WHICH == 2) ? 64 : 128;
    float* wT    = (WHICH == 2) ? g_wT2 : g_wT3;
    float* shift = (WHICH == 2) ? g_shift2 : g_shift3;
    int idx = blockIdx.x * 256 + threadIdx.x;
    const int total = CIN * 27 * COUT;
    if (idx < total) {
        int o = idx % COUT;
        int r = idx / COUT;
        int c = r % CIN;
        int tap = r / CIN;
        float s = rsqrtf(bnv[o] + BN_EPS) * bng[o];
        wT[idx] = w[((size_t)o * CIN + c) * 27 + tap] * s;
    }
    if (idx < COUT) {
        float s = rsqrtf(bnv[idx] + BN_EPS) * bng[idx];
        shift[idx] = (bias[idx] - bnm[idx]) * s + bnb[idx];
    }
}

// ================= bf16-split conversion =================
__global__ void cvt_x_kernel(const float* __restrict__ x) {
    int i = blockIdx.x * 256 + threadIdx.x;
    if (i < 1310720) {
        float v = x[i];
        __nv_bfloat16 h = __float2bfloat16_rn(v);
        g_xh[i] = h;
        g_xl[i] = __float2bfloat16_rn(v - __bfloat162float(h));
    }
}

__global__ void trans_w1_kernel(const float* __restrict__ w1) {
    __shared__ float tile[32][33];
    int e = blockIdx.z;
    int j0 = blockIdx.x * 32, d0 = blockIdx.y * 32;
    const float* W = w1 + (size_t)e * 13107200;
    int tx = threadIdx.x, ty = threadIdx.y;
#pragma unroll
    for (int r = 0; r < 32; r += 8)
        tile[ty + r][tx] = W[(size_t)(d0 + ty + r) * 10240 + j0 + tx];
    __syncthreads();
#pragma unroll
    for (int r = 0; r < 32; r += 8) {
        float v = tile[tx][ty + r];
        size_t o = (size_t)(e * 10240 + j0 + ty + r) * 1280 + d0 + tx;
        __nv_bfloat16 h = __float2bfloat16_rn(v);
        g_w1h[o] = h;
        g_w1l[o] = __float2bfloat16_rn(v - __bfloat162float(h));
    }
}

__global__ void trans_w2_kernel(const float* __restrict__ w2) {
    __shared__ float tile[32][33];
    int e = blockIdx.z;
    int j0 = blockIdx.x * 32, i0 = blockIdx.y * 32;
    const float* W = w2 + (size_t)e * 6553600;
    int tx = threadIdx.x, ty = threadIdx.y;
#pragma unroll
    for (int r = 0; r < 32; r += 8)
        tile[ty + r][tx] = W[(size_t)(i0 + ty + r) * 1280 + j0 + tx];
    __syncthreads();
#pragma unroll
    for (int r = 0; r < 32; r += 8) {
        float v = tile[tx][ty + r];
        size_t o = (size_t)(j0 + ty + r) * 20480 + e * 5120 + i0 + tx;
        __nv_bfloat16 h = __float2bfloat16_rn(v);
        g_w2h[o] = h;
        g_w2l[o] = __float2bfloat16_rn(v - __bfloat162float(h));
    }
}

// ================= conv1: channels-last output =================
__global__ void conv1_kernel(const float* __restrict__ mask,
                             const float* __restrict__ w, const float* __restrict__ bias,
                             const float* __restrict__ bng, const float* __restrict__ bnb,
                             const float* __restrict__ bnm, const float* __restrict__ bnv) {
    __shared__ float ws[32][27];
    __shared__ float sscale[32], sshift[32];
    int t = threadIdx.x;
    if (t < 32) {
        float s = rsqrtf(bnv[t] + BN_EPS) * bng[t];
        sscale[t] = s;
        sshift[t] = (bias[t] - bnm[t]) * s + bnb[t];
    }
    __syncthreads();
    for (int idx = t; idx < 864; idx += 256) {
        int o = idx / 27, tap = idx % 27;
        ws[o][tap] = w[idx] * sscale[o];
    }
    __syncthreads();

    int b = blockIdx.x, d = blockIdx.y;
    int h = t >> 4, wq = t & 15;
    const float* mb = mask + (size_t)b * 16384;

    float v[27];
#pragma unroll
    for (int kd = 0; kd < 3; kd++)
#pragma unroll
        for (int kh = 0; kh < 3; kh++)
#pragma unroll
            for (int kw = 0; kw < 3; kw++) {
                int zd = 2 * d - 1 + kd, zh = 2 * h - 1 + kh, zw = 2 * wq - 1 + kw;
                bool ok = (unsigned)zd < 16u && (unsigned)zh < 32u && (unsigned)zw < 32u;
                v[(kd * 3 + kh) * 3 + kw] = ok ? mb[zd * 1024 + zh * 32 + zw] : 0.f;
            }

    float o32[32];
#pragma unroll
    for (int o = 0; o < 32; o++) {
        float acc = 0.f;
#pragma unroll
        for (int tap = 0; tap < 27; tap++) acc = fmaf(ws[o][tap], v[tap], acc);
        o32[o] = fmaxf(acc + sshift[o], 0.f);
    }
    float* op = g_m1 + ((((size_t)b * 8 + d) * 256) + t) * 32;
#pragma unroll
    for (int q = 0; q < 8; q++)
        *(float4*)(op + q * 4) = make_float4(o32[q * 4], o32[q * 4 + 1],
                                             o32[q * 4 + 2], o32[q * 4 + 3]);
}

// ================= conv2/3 channels-last implicit GEMM =================
template<int WHICH>
__global__ void conv_gemm_kernel() {
    constexpr int CIN  = (WHICH == 2) ? 32 : 64;
    constexpr int COUT = (WHICH == 2) ? 64 : 128;
    constexpr int DIN  = (WHICH == 2) ? 8 : 4;
    constexpr int HIN  = (WHICH == 2) ? 16 : 8;
    constexpr int WIN  = (WHICH == 2) ? 16 : 8;
    constexpr int HOUT = (WHICH == 2) ? 8 : 4;
    constexpr int WOUT = (WHICH == 2) ? 8 : 4;
    constexpr int DHW  = DIN * HIN * WIN;
    constexpr int POS  = ((WHICH == 2) ? 4 : 2) * HOUT * WOUT;
    constexpr int CINQ = CIN / 4;

    const float* in    = (WHICH == 2) ? g_m1 : g_m2;
    const float* wT    = (WHICH == 2) ? g_wT2 : g_wT3;
    const float* shift = (WHICH == 2) ? g_shift2 : g_shift3;
    float*       out   = (WHICH == 2) ? g_m2 : g_m3;

    __shared__ float As[CIN][68];
    __shared__ float Bs[CIN][68];
    __shared__ int   offs[27];

    int pos = blockIdx.x;
    int t = threadIdx.x;
    if (t < 27) {
        int d = pos / (HOUT * WOUT);
        int rem = pos % (HOUT * WOUT);
        int h = rem / WOUT, w = rem % WOUT;
        int kd = t / 9, r = t % 9, kh = r / 3, kw = r % 3;
        int zd = 2 * d - 1 + kd, zh = 2 * h - 1 + kh, zw = 2 * w - 1 + kw;
        bool ok = (unsigned)zd < (unsigned)DIN && (unsigned)zh < (unsigned)HIN &&
                  (unsigned)zw < (unsigned)WIN;
        offs[t] = ok ? ((zd * HIN + zh) * WIN + zw) : -1;
    }
    __syncthreads();

    int b0 = blockIdx.y * 64;
    int o0 = blockIdx.z * 64;
    int tx = t & 15, ty = t >> 4;
    float acc[4][4] = {};

    for (int tap = 0; tap < 27; tap++) {
        int off = offs[tap];
        if (off < 0) continue;
        __syncthreads();
        const float* ibase = in + (size_t)off * CIN;
#pragma unroll
        for (int i = 0; i < CINQ / 4; i++) {
            int idx = t + 256 * i;
            int bb = idx / CINQ, c4 = idx % CINQ;
            float4 v = *(const float4*)(ibase + (size_t)(b0 + bb) * (DHW * CIN) + c4 * 4);
            As[c4 * 4 + 0][bb] = v.x;
            As[c4 * 4 + 1][bb] = v.y;
            As[c4 * 4 + 2][bb] = v.z;
            As[c4 * 4 + 3][bb] = v.w;
        }
        const float* wb = wT + (size_t)tap * CIN * COUT + o0;
#pragma unroll
        for (int i = 0; i < CINQ / 4; i++) {
            int idx = t + 256 * i;
            int c = idx / 16, o4 = idx % 16;
            *(float4*)&Bs[c][o4 * 4] = *(const float4*)(wb + (size_t)c * COUT + o4 * 4);
        }
        __syncthreads();
#pragma unroll
        for (int k = 0; k < CIN; k++) {
            float4 a4 = *(const float4*)&As[k][ty * 4];
            float4 b4 = *(const float4*)&Bs[k][tx * 4];
            float a[4] = {a4.x, a4.y, a4.z, a4.w};
            float b[4] = {b4.x, b4.y, b4.z, b4.w};
#pragma unroll
            for (int i = 0; i < 4; i++)
#pragma unroll
                for (int j = 0; j < 4; j++)
                    acc[i][j] = fmaf(a[i], b[j], acc[i][j]);
        }
    }

#pragma unroll
    for (int i = 0; i < 4; i++) {
        int b = b0 + ty * 4 + i;
        float* op = out + ((size_t)b * POS + pos) * COUT + o0 + tx * 4;
        float4 v;
        v.x = fmaxf(acc[i][0] + shift[o0 + tx * 4 + 0], 0.f);
        v.y = fmaxf(acc[i][1] + shift[o0 + tx * 4 + 1], 0.f);
        v.z = fmaxf(acc[i][2] + shift[o0 + tx * 4 + 2], 0.f);
        v.w = fmaxf(acc[i][3] + shift[o0 + tx * 4 + 3], 0.f);
        *(float4*)op = v;
    }
}

// ================= gate =================
__global__ void gate_kernel(const float* __restrict__ fc_w, const float* __restrict__ fc_b) {
    int b = blockIdx.x, t = threadIdx.x;
    __shared__ float pooled[128];
    __shared__ float logit[4];
    const float* p = g_m3 + (size_t)b * 4096 + t;
    float s = 0.f;
#pragma unroll
    for (int i = 0; i < 32; i++) s += p[i * 128];
    pooled[t] = s * (1.0f / 32.0f);
    __syncthreads();
    if (t < 4) {
        float l = fc_b[t];
        const float* wrow = fc_w + t * 128;
        for (int c = 0; c < 128; c++) l = fmaf(pooled[c], wrow[c], l);
        logit[t] = l;
    }
    __syncthreads();
    if (t == 0) {
        float mx = fmaxf(fmaxf(logit[0], logit[1]), fmaxf(logit[2], logit[3]));
        float e0 = expf(logit[0] - mx), e1 = expf(logit[1] - mx);
        float e2 = expf(logit[2] - mx), e3 = expf(logit[3] - mx);
        float inv = 1.f / (e0 + e1 + e2 + e3);
        g_gw[b * 4 + 0] = e0 * inv;
        g_gw[b * 4 + 1] = e1 * inv;
        g_gw[b * 4 + 2] = e2 * inv;
        g_gw[b * 4 + 3] = e3 * inv;
    }
}

// ================= mma.sync GEMM, 4-stage kT=16 pipeline =================
// MODE 1 = GEGLU (hid stored UNscaled), MODE 2 = per-expert output GEMM (z = expert)
#define TILE_B   6144     // 128 rows * 48B
#define STAGE_B  24576    // 4 tiles
#define NSTAGE   4
#define SMEM_BYTES 98304  // 4 stages

template<int MODE>
__global__ void __launch_bounds__(256, 2) mma_gemm_kernel(const float* __restrict__ b1) {
    extern __shared__ char smem[];
    unsigned sb = smem_u32(smem);
    int t = threadIdx.x, wid = t >> 5, lid = t & 31;

    constexpr int KT = (MODE == 1) ? 80 : 320;

    int m0 = blockIdx.x * 128;
    int e = 0, h0 = 0, n0 = 0;
    size_t kbase = 0;
    if (MODE == 1) { e = blockIdx.y / 80; h0 = (blockIdx.y % 80) * 64; }
    else           { n0 = blockIdx.y * 128; e = blockIdx.z; kbase = (size_t)e * 5120; }

    // per-thread cp.async slots: 1024 16B-chunks / 256 threads = 4 each
    const __nv_bfloat16* gsrc[4];
    unsigned sdst[4];
#pragma unroll
    for (int i = 0; i < 4; i++) {
        int c = t + 256 * i;
        int tile = c >> 8, rs = c & 255, row = rs >> 1, seg = rs & 1;
        const __nv_bfloat16* base;
        size_t grow;
        if (MODE == 1) {
            if (tile < 2) {
                base = tile ? g_xl : g_xh;
                grow = (size_t)(m0 + row) * 1280;
            } else {
                int g = e * 10240 + (row & 1) * 5120 + h0 + (row >> 1);
                base = (tile == 2) ? g_w1h : g_w1l;
                grow = (size_t)g * 1280;
            }
        } else {
            if (tile < 2) {
                base = tile ? g_hl : g_hh;
                grow = (size_t)(m0 + row) * 20480;
            } else {
                base = (tile == 2) ? g_w2h : g_w2l;
                grow = (size_t)(n0 + row) * 20480;
            }
        }
        gsrc[i] = base + grow + seg * 8;
        sdst[i] = sb + tile * TILE_B + row * 48 + seg * 16;
    }

    // prologue: stages 0..2
#pragma unroll
    for (int st = 0; st < NSTAGE - 1; st++) {
        size_t k0 = kbase + st * 16;
#pragma unroll
        for (int i = 0; i < 4; i++) CP_ASYNC16(sdst[i] + st * STAGE_B, gsrc[i] + k0);
        CP_COMMIT();
    }

    float cacc[2][8][4];
#pragma unroll
    for (int mf = 0; mf < 2; mf++)
#pragma unroll
        for (int nf = 0; nf < 8; nf++)
#pragma unroll
            for (int q = 0; q < 4; q++) cacc[mf][nf][q] = 0.f;

    unsigned warpM = (wid & 3) * 32;
    unsigned warpN = (wid >> 2) * 64;

    for (int kt = 0; kt < KT; kt++) {
        CP_WAIT2();
        __syncthreads();
        // issue stage kt+3 into slot (kt+3)&3 (consumed at kt-1, fenced by trailing sync)
        int ktn = kt + NSTAGE - 1;
        if (ktn < KT) {
            size_t k0 = kbase + (size_t)ktn * 16;
            unsigned so = (ktn & 3) * STAGE_B;
#pragma unroll
            for (int i = 0; i < 4; i++) CP_ASYNC16(sdst[i] + so, gsrc[i] + k0);
        }
        CP_COMMIT();

        unsigned sA_H = sb + (kt & 3) * STAGE_B;
        unsigned sA_L = sA_H + TILE_B;
        unsigned sB_H = sA_H + 2 * TILE_B;
        unsigned sB_L = sA_H + 3 * TILE_B;

        unsigned aH[2][4], aL[2][4];
#pragma unroll
        for (int mf = 0; mf < 2; mf++) {
            unsigned off = (warpM + mf * 16 + (lid & 15)) * 48 + (lid >> 4) * 16;
            ldsm4(aH[mf], sA_H + off);
            ldsm4(aL[mf], sA_L + off);
        }
#pragma unroll
        for (int nf2 = 0; nf2 < 4; nf2++) {
            unsigned off = (warpN + nf2 * 16 + (lid & 7) + ((lid >> 4) & 1) * 8) * 48 +
                           ((lid >> 3) & 1) * 16;
            unsigned rH[4], rL[4];
            ldsm4(rH, sB_H + off);
            ldsm4(rL, sB_L + off);
#pragma unroll
            for (int mf = 0; mf < 2; mf++) {
                MMA16816(cacc[mf][2 * nf2],     aH[mf], rH[0], rH[1]);
                MMA16816(cacc[mf][2 * nf2],     aH[mf], rL[0], rL[1]);
                MMA16816(cacc[mf][2 * nf2],     aL[mf], rH[0], rH[1]);
                MMA16816(cacc[mf][2 * nf2 + 1], aH[mf], rH[2], rH[3]);
                MMA16816(cacc[mf][2 * nf2 + 1], aH[mf], rL[2], rL[3]);
                MMA16816(cacc[mf][2 * nf2 + 1], aL[mf], rH[2], rH[3]);
            }
        }
        __syncthreads();
    }

    int grp = lid >> 2, qd = lid & 3;
    if (MODE == 1) {
        const float* bv = b1 + (size_t)e * 10240;
#pragma unroll
        for (int mf = 0; mf < 2; mf++) {
#pragma unroll
            for (int half = 0; half < 2; half++) {
                int n = m0 + warpM + mf * 16 + grp + half * 8;
                size_t ob = (size_t)n * 20480 + (size_t)e * 5120;
#pragma unroll
                for (int nf = 0; nf < 8; nf++) {
                    int h = h0 + (warpN >> 1) + nf * 4 + qd;
                    float val  = cacc[mf][nf][half * 2 + 0];
                    float gate = cacc[mf][nf][half * 2 + 1];
                    float v = val + bv[h];
                    float g = gate + bv[5120 + h];
                    float hid = v * (0.5f * g * (1.f + erff(g * 0.70710678118654752f)));
                    __nv_bfloat16 hh = __float2bfloat16_rn(hid);
                    g_hh[ob + h] = hh;
                    g_hl[ob + h] = __float2bfloat16_rn(hid - __bfloat162float(hh));
                }
            }
        }
    } else {
        size_t zb = (size_t)e * 1310720;
#pragma unroll
        for (int mf = 0; mf < 2; mf++) {
#pragma unroll
            for (int half = 0; half < 2; half++) {
                int n = m0 + warpM + mf * 16 + grp + half * 8;
                size_t rb = zb + (size_t)n * 1280;
#pragma unroll
                for (int nf = 0; nf < 8; nf++) {
                    int col = n0 + warpN + nf * 8 + qd * 2;
                    g_part[rb + col]     = cacc[mf][nf][half * 2 + 0];
                    g_part[rb + col + 1] = cacc[mf][nf][half * 2 + 1];
                }
            }
        }
    }
}

// ================= reduce: gate-weighted expert sum + bias =================
__global__ void reduce_kernel(const float* __restrict__ b2, float* __restrict__ out) {
    int i = blockIdx.x * 256 + threadIdx.x;
    int n = i / 1280, j = i - n * 1280;
    const float* gw = g_gw + n * 4;
    float s = gw[0] * (g_part[i]           + b2[j]) +
              gw[1] * (g_part[1310720 + i] + b2[1280 + j]) +
              gw[2] * (g_part[2621440 + i] + b2[2560 + j]) +
              gw[3] * (g_part[3932160 + i] + b2[3840 + j]);
    out[i] = s;
}

// ================= launch =================
extern "C" void kernel_launch(void* const* d_in, const int* in_sizes, int n_in,
                              void* d_out, int out_size) {
    const float* x    = (const float*)d_in[0];
    const float* mask = (const float*)d_in[1];
    const float* c1w  = (const float*)d_in[2];
    const float* c1b  = (const float*)d_in[3];
    const float* bn1g = (const float*)d_in[4];
    const float* bn1b = (const float*)d_in[5];
    const float* bn1m = (const float*)d_in[6];
    const float* bn1v = (const float*)d_in[7];
    const float* c2w  = (const float*)d_in[8];
    const float* c2b  = (const float*)d_in[9];
    const float* bn2g = (const float*)d_in[10];
    const float* bn2b = (const float*)d_in[11];
    const float* bn2m = (const float*)d_in[12];
    const float* bn2v = (const float*)d_in[13];
    const float* c3w  = (const float*)d_in[14];
    const float* c3b  = (const float*)d_in[15];
    const float* bn3g = (const float*)d_in[16];
    const float* bn3b = (const float*)d_in[17];
    const float* bn3m = (const float*)d_in[18];
    const float* bn3v = (const float*)d_in[19];
    const float* fcw  = (const float*)d_in[20];
    const float* fcb  = (const float*)d_in[21];
    const float* w1   = (const float*)d_in[22];
    const float* b1   = (const float*)d_in[23];
    const float* w2   = (const float*)d_in[24];
    const float* b2   = (const float*)d_in[25];
    float* out = (float*)d_out;

    cudaFuncSetAttribute(mma_gemm_kernel<1>, cudaFuncAttributeMaxDynamicSharedMemorySize, SMEM_BYTES);
    cudaFuncSetAttribute(mma_gemm_kernel<2>, cudaFuncAttributeMaxDynamicSharedMemorySize, SMEM_BYTES);

    prep_kernel<2><<<216, 256>>>(c2w, c2b, bn2g, bn2b, bn2m, bn2v);
    prep_kernel<3><<<864, 256>>>(c3w, c3b, bn3g, bn3b, bn3m, bn3v);
    cvt_x_kernel<<<5120, 256>>>(x);
    trans_w1_kernel<<<dim3(320, 40, 4), dim3(32, 8)>>>(w1);
    trans_w2_kernel<<<dim3(40, 160, 4), dim3(32, 8)>>>(w2);
    conv1_kernel<<<dim3(1024, 8), 256>>>(mask, c1w, c1b, bn1g, bn1b, bn1m, bn1v);
    conv_gemm_kernel<2><<<dim3(256, 16, 1), 256>>>();
    conv_gemm_kernel<3><<<dim3(32, 16, 2), 256>>>();
    gate_kernel<<<1024, 128>>>(fcw, fcb);
    mma_gemm_kernel<1><<<dim3(8, 320), 256, SMEM_BYTES>>>(b1);
    mma_gemm_kernel<2><<<dim3(8, 10, 4), 256, SMEM_BYTES>>>(b1);
    reduce_kernel<<<5120, 256>>>(b2, out);
}

// round 12
// speedup vs baseline: 1.1268x; 1.1268x over previous
#include <cuda_runtime.h>
#include <cuda_bf16.h>
#include <math.h>

#define BN_EPS 1e-5f

// ================= scratch =================
__device__ float g_m1[67108864];   // conv1 out, channels-last [1024][8][16][16][32]
__device__ float g_m2[16777216];   // conv2 out, channels-last [1024][256][64]
__device__ float g_m3[4194304];    // conv3 out, channels-last [1024][32][128]
__device__ float g_wT2[55296];     // [tap27][c32][o64]
__device__ float g_shift2[64];
__device__ float g_wT3[221184];    // [tap27][c64][o128]
__device__ float g_shift3[128];
__device__ float g_gw[4096];       // [1024][4]
// bf16 split operands
__device__ __nv_bfloat16 g_xh[1310720],  g_xl[1310720];    // x [1024][1280]
__device__ __nv_bfloat16 g_w1h[52428800], g_w1l[52428800]; // W1^T [40960][1280]
__device__ __nv_bfloat16 g_w2h[26214400], g_w2l[26214400]; // W2^T [1280][20480]
__device__ __nv_bfloat16 g_hh[20971520],  g_hl[20971520];  // hid [1024][20480] (UNscaled)
__device__ float g_part[20971520]; // [16 = e*4+ksplit][1024][1280] partials

// ================= helpers =================
__device__ __forceinline__ unsigned smem_u32(const void* ptr) {
    unsigned a;
    asm("{ .reg .u64 t; cvta.to.shared.u64 t, %1; cvt.u32.u64 %0, t; }" : "=r"(a) : "l"(ptr));
    return a;
}
#define CP_ASYNC16(dst, src) \
    asm volatile("cp.async.cg.shared.global [%0], [%1], 16;" :: "r"(dst), "l"(src))
#define CP_COMMIT() asm volatile("cp.async.commit_group;" ::: "memory")
#define CP_WAIT1()  asm volatile("cp.async.wait_group 1;" ::: "memory")

__device__ __forceinline__ void ldsm4(unsigned* r, unsigned addr) {
    asm volatile("ldmatrix.sync.aligned.m8n8.x4.shared.b16 {%0,%1,%2,%3}, [%4];"
                 : "=r"(r[0]), "=r"(r[1]), "=r"(r[2]), "=r"(r[3]) : "r"(addr));
}
#define MMA16816(c, a, b0v, b1v) \
    asm volatile("mma.sync.aligned.m16n8k16.row.col.f32.bf16.bf16.f32 " \
        "{%0,%1,%2,%3}, {%4,%5,%6,%7}, {%8,%9}, {%0,%1,%2,%3};" \
        : "+f"((c)[0]), "+f"((c)[1]), "+f"((c)[2]), "+f"((c)[3]) \
        : "r"((a)[0]), "r"((a)[1]), "r"((a)[2]), "r"((a)[3]), "r"(b0v), "r"(b1v))

// ================= prep: conv weights + BN fold -> [tap][c][o] =================
template<int WHICH>
__global__ void prep_kernel(const float* __restrict__ w, const float* __restrict__ bias,
                            const float* __restrict__ bng, const float* __restrict__ bnb,
                            const float* __restrict__ bnm, const float* __restrict__ bnv) {
    constexpr int CIN  = (WHICH == 2) ? 32 : 64;
    constexpr int COUT = (WHICH == 2) ? 64 : 128;
    float* wT    = (WHICH == 2) ? g_wT2 : g_wT3;
    float* shift = (WHICH == 2) ? g_shift2 : g_shift3;
    int idx = blockIdx.x * 256 + threadIdx.x;
    const int total = CIN * 27 * COUT;
    if (idx < total) {
        int o = idx % COUT;
        int r = idx / COUT;
        int c = r % CIN;
        int tap = r / CIN;
        float s = rsqrtf(bnv[o] + BN_EPS) * bng[o];
        wT[idx] = w[((size_t)o * CIN + c) * 27 + tap] * s;
    }
    if (idx < COUT) {
        float s = rsqrtf(bnv[idx] + BN_EPS) * bng[idx];
        shift[idx] = (bias[idx] - bnm[idx]) * s + bnb[idx];
    }
}

// ================= bf16-split conversion =================
__global__ void cvt_x_kernel(const float* __restrict__ x) {
    int i = blockIdx.x * 256 + threadIdx.x;
    if (i < 1310720) {
        float v = x[i];
        __nv_bfloat16 h = __float2bfloat16_rn(v);
        g_xh[i] = h;
        g_xl[i] = __float2bfloat16_rn(v - __bfloat162float(h));
    }
}

__global__ void trans_w1_kernel(const float* __restrict__ w1) {
    __shared__ float tile[32][33];
    int e = blockIdx.z;
    int j0 = blockIdx.x * 32, d0 = blockIdx.y * 32;
    const float* W = w1 + (size_t)e * 13107200;
    int tx = threadIdx.x, ty = threadIdx.y;
#pragma unroll
    for (int r = 0; r < 32; r += 8)
        tile[ty + r][tx] = W[(size_t)(d0 + ty + r) * 10240 + j0 + tx];
    __syncthreads();
#pragma unroll
    for (int r = 0; r < 32; r += 8) {
        float v = tile[tx][ty + r];
        size_t o = (size_t)(e * 10240 + j0 + ty + r) * 1280 + d0 + tx;
        __nv_bfloat16 h = __float2bfloat16_rn(v);
        g_w1h[o] = h;
        g_w1l[o] = __float2bfloat16_rn(v - __bfloat162float(h));
    }
}

__global__ void trans_w2_kernel(const float* __restrict__ w2) {
    __shared__ float tile[32][33];
    int e = blockIdx.z;
    int j0 = blockIdx.x * 32, i0 = blockIdx.y * 32;
    const float* W = w2 + (size_t)e * 6553600;
    int tx = threadIdx.x, ty = threadIdx.y;
#pragma unroll
    for (int r = 0; r < 32; r += 8)
        tile[ty + r][tx] = W[(size_t)(i0 + ty + r) * 1280 + j0 + tx];
    __syncthreads();
#pragma unroll
    for (int r = 0; r < 32; r += 8) {
        float v = tile[tx][ty + r];
        size_t o = (size_t)(j0 + ty + r) * 20480 + e * 5120 + i0 + tx;
        __nv_bfloat16 h = __float2bfloat16_rn(v);
        g_w2h[o] = h;
        g_w2l[o] = __float2bfloat16_rn(v - __bfloat162float(h));
    }
}

// ================= conv1: channels-last output =================
__global__ void conv1_kernel(const float* __restrict__ mask,
                             const float* __restrict__ w, const float* __restrict__ bias,
                             const float* __restrict__ bng, const float* __restrict__ bnb,
                             const float* __restrict__ bnm, const float* __restrict__ bnv) {
    __shared__ float ws[32][27];
    __shared__ float sscale[32], sshift[32];
    int t = threadIdx.x;
    if (t < 32) {
        float s = rsqrtf(bnv[t] + BN_EPS) * bng[t];
        sscale[t] = s;
        sshift[t] = (bias[t] - bnm[t]) * s + bnb[t];
    }
    __syncthreads();
    for (int idx = t; idx < 864; idx += 256) {
        int o = idx / 27, tap = idx % 27;
        ws[o][tap] = w[idx] * sscale[o];
    }
    __syncthreads();

    int b = blockIdx.x, d = blockIdx.y;
    int h = t >> 4, wq = t & 15;
    const float* mb = mask + (size_t)b * 16384;

    float v[27];
#pragma unroll
    for (int kd = 0; kd < 3; kd++)
#pragma unroll
        for (int kh = 0; kh < 3; kh++)
#pragma unroll
            for (int kw = 0; kw < 3; kw++) {
                int zd = 2 * d - 1 + kd, zh = 2 * h - 1 + kh, zw = 2 * wq - 1 + kw;
                bool ok = (unsigned)zd < 16u && (unsigned)zh < 32u && (unsigned)zw < 32u;
                v[(kd * 3 + kh) * 3 + kw] = ok ? mb[zd * 1024 + zh * 32 + zw] : 0.f;
            }

    float o32[32];
#pragma unroll
    for (int o = 0; o < 32; o++) {
        float acc = 0.f;
#pragma unroll
        for (int tap = 0; tap < 27; tap++) acc = fmaf(ws[o][tap], v[tap], acc);
        o32[o] = fmaxf(acc + sshift[o], 0.f);
    }
    float* op = g_m1 + ((((size_t)b * 8 + d) * 256) + t) * 32;
#pragma unroll
    for (int q = 0; q < 8; q++)
        *(float4*)(op + q * 4) = make_float4(o32[q * 4], o32[q * 4 + 1],
                                             o32[q * 4 + 2], o32[q * 4 + 3]);
}

// ================= conv2/3 channels-last implicit GEMM =================
template<int WHICH>
__global__ void conv_gemm_kernel() {
    constexpr int CIN  = (WHICH == 2) ? 32 : 64;
    constexpr int COUT = (WHICH == 2) ? 64 : 128;
    constexpr int DIN  = (WHICH == 2) ? 8 : 4;
    constexpr int HIN  = (WHICH == 2) ? 16 : 8;
    constexpr int WIN  = (WHICH == 2) ? 16 : 8;
    constexpr int HOUT = (WHICH == 2) ? 8 : 4;
    constexpr int WOUT = (WHICH == 2) ? 8 : 4;
    constexpr int DHW  = DIN * HIN * WIN;
    constexpr int POS  = ((WHICH == 2) ? 4 : 2) * HOUT * WOUT;
    constexpr int CINQ = CIN / 4;

    const float* in    = (WHICH == 2) ? g_m1 : g_m2;
    const float* wT    = (WHICH == 2) ? g_wT2 : g_wT3;
    const float* shift = (WHICH == 2) ? g_shift2 : g_shift3;
    float*       out   = (WHICH == 2) ? g_m2 : g_m3;

    __shared__ float As[CIN][68];
    __shared__ float Bs[CIN][68];
    __shared__ int   offs[27];

    int pos = blockIdx.x;
    int t = threadIdx.x;
    if (t < 27) {
        int d = pos / (HOUT * WOUT);
        int rem = pos % (HOUT * WOUT);
        int h = rem / WOUT, w = rem % WOUT;
        int kd = t / 9, r = t % 9, kh = r / 3, kw = r % 3;
        int zd = 2 * d - 1 + kd, zh = 2 * h - 1 + kh, zw = 2 * w - 1 + kw;
        bool ok = (unsigned)zd < (unsigned)DIN && (unsigned)zh < (unsigned)HIN &&
                  (unsigned)zw < (unsigned)WIN;
        offs[t] = ok ? ((zd * HIN + zh) * WIN + zw) : -1;
    }
    __syncthreads();

    int b0 = blockIdx.y * 64;
    int o0 = blockIdx.z * 64;
    int tx = t & 15, ty = t >> 4;
    float acc[4][4] = {};

    for (int tap = 0; tap < 27; tap++) {
        int off = offs[tap];
        if (off < 0) continue;
        __syncthreads();
        const float* ibase = in + (size_t)off * CIN;
#pragma unroll
        for (int i = 0; i < CINQ / 4; i++) {
            int idx = t + 256 * i;
            int bb = idx / CINQ, c4 = idx % CINQ;
            float4 v = *(const float4*)(ibase + (size_t)(b0 + bb) * (DHW * CIN) + c4 * 4);
            As[c4 * 4 + 0][bb] = v.x;
            As[c4 * 4 + 1][bb] = v.y;
            As[c4 * 4 + 2][bb] = v.z;
            As[c4 * 4 + 3][bb] = v.w;
        }
        const float* wb = wT + (size_t)tap * CIN * COUT + o0;
#pragma unroll
        for (int i = 0; i < CINQ / 4; i++) {
            int idx = t + 256 * i;
            int c = idx / 16, o4 = idx % 16;
            *(float4*)&Bs[c][o4 * 4] = *(const float4*)(wb + (size_t)c * COUT + o4 * 4);
        }
        __syncthreads();
#pragma unroll
        for (int k = 0; k < CIN; k++) {
            float4 a4 = *(const float4*)&As[k][ty * 4];
            float4 b4 = *(const float4*)&Bs[k][tx * 4];
            float a[4] = {a4.x, a4.y, a4.z, a4.w};
            float b[4] = {b4.x, b4.y, b4.z, b4.w};
#pragma unroll
            for (int i = 0; i < 4; i++)
#pragma unroll
                for (int j = 0; j < 4; j++)
                    acc[i][j] = fmaf(a[i], b[j], acc[i][j]);
        }
    }

#pragma unroll
    for (int i = 0; i < 4; i++) {
        int b = b0 + ty * 4 + i;
        float* op = out + ((size_t)b * POS + pos) * COUT + o0 + tx * 4;
        float4 v;
        v.x = fmaxf(acc[i][0] + shift[o0 + tx * 4 + 0], 0.f);
        v.y = fmaxf(acc[i][1] + shift[o0 + tx * 4 + 1], 0.f);
        v.z = fmaxf(acc[i][2] + shift[o0 + tx * 4 + 2], 0.f);
        v.w = fmaxf(acc[i][3] + shift[o0 + tx * 4 + 3], 0.f);
        *(float4*)op = v;
    }
}

// ================= gate =================
__global__ void gate_kernel(const float* __restrict__ fc_w, const float* __restrict__ fc_b) {
    int b = blockIdx.x, t = threadIdx.x;
    __shared__ float pooled[128];
    __shared__ float logit[4];
    const float* p = g_m3 + (size_t)b * 4096 + t;
    float s = 0.f;
#pragma unroll
    for (int i = 0; i < 32; i++) s += p[i * 128];
    pooled[t] = s * (1.0f / 32.0f);
    __syncthreads();
    if (t < 4) {
        float l = fc_b[t];
        const float* wrow = fc_w + t * 128;
        for (int c = 0; c < 128; c++) l = fmaf(pooled[c], wrow[c], l);
        logit[t] = l;
    }
    __syncthreads();
    if (t == 0) {
        float mx = fmaxf(fmaxf(logit[0], logit[1]), fmaxf(logit[2], logit[3]));
        float e0 = expf(logit[0] - mx), e1 = expf(logit[1] - mx);
        float e2 = expf(logit[2] - mx), e3 = expf(logit[3] - mx);
        float inv = 1.f / (e0 + e1 + e2 + e3);
        g_gw[b * 4 + 0] = e0 * inv;
        g_gw[b * 4 + 1] = e1 * inv;
        g_gw[b * 4 + 2] = e2 * inv;
        g_gw[b * 4 + 3] = e3 * inv;
    }
}

// ================= mma.sync GEMM, 2-stage kT=32 (R7-proven) =================
// MODE 1 = GEGLU (hid UNscaled), MODE 2 = per-expert output GEMM with split-K x4
#define TILE_B   10240
#define STAGE_B  40960
#define SMEM_BYTES 81920

template<int MODE>
__global__ void __launch_bounds__(256, 2) mma_gemm_kernel(const float* __restrict__ b1) {
    extern __shared__ char smem[];
    unsigned sb = smem_u32(smem);
    int t = threadIdx.x, wid = t >> 5, lid = t & 31;

    constexpr int KT = 40;  // MODE1: 1280 K; MODE2: 1280 K per split

    int m0 = blockIdx.x * 128;
    int e = 0, h0 = 0, n0 = 0, z = 0;
    size_t kbase = 0;
    if (MODE == 1) { e = blockIdx.y / 80; h0 = (blockIdx.y % 80) * 64; }
    else {
        n0 = blockIdx.y * 128;
        z = blockIdx.z;                 // 0..15 = e*4 + ksplit
        kbase = (size_t)(z >> 2) * 5120 + (size_t)(z & 3) * 1280;
    }

    const __nv_bfloat16* gsrc[8];
    unsigned sdst[8];
#pragma unroll
    for (int i = 0; i < 8; i++) {
        int c = t + 256 * i;
        int tile = c >> 9, rs = c & 511, row = rs >> 2, seg = rs & 3;
        const __nv_bfloat16* base;
        size_t grow;
        if (MODE == 1) {
            if (tile < 2) {
                base = tile ? g_xl : g_xh;
                grow = (size_t)(m0 + row) * 1280;
            } else {
                int g = e * 10240 + (row & 1) * 5120 + h0 + (row >> 1);
                base = (tile == 2) ? g_w1h : g_w1l;
                grow = (size_t)g * 1280;
            }
        } else {
            if (tile < 2) {
                base = tile ? g_hl : g_hh;
                grow = (size_t)(m0 + row) * 20480;
            } else {
                base = (tile == 2) ? g_w2h : g_w2l;
                grow = (size_t)(n0 + row) * 20480;
            }
        }
        gsrc[i] = base + grow + seg * 8;
        sdst[i] = sb + tile * TILE_B + row * 80 + seg * 16;
    }

#pragma unroll
    for (int st = 0; st < 2; st++) {
        size_t k0 = kbase + st * 32;
#pragma unroll
        for (int i = 0; i < 8; i++) CP_ASYNC16(sdst[i] + st * STAGE_B, gsrc[i] + k0);
        CP_COMMIT();
    }

    float cacc[2][8][4];
#pragma unroll
    for (int mf = 0; mf < 2; mf++)
#pragma unroll
        for (int nf = 0; nf < 8; nf++)
#pragma unroll
            for (int q = 0; q < 4; q++) cacc[mf][nf][q] = 0.f;

    unsigned warpM = (wid & 3) * 32;
    unsigned warpN = (wid >> 2) * 64;

    for (int kt = 0; kt < KT; kt++) {
        CP_WAIT1();
        __syncthreads();
        int st = kt & 1;
        unsigned sA_H = sb + st * STAGE_B;
        unsigned sA_L = sA_H + TILE_B;
        unsigned sB_H = sA_H + 2 * TILE_B;
        unsigned sB_L = sA_H + 3 * TILE_B;

#pragma unroll
        for (int ks = 0; ks < 2; ks++) {
            unsigned aH[2][4], aL[2][4];
#pragma unroll
            for (int mf = 0; mf < 2; mf++) {
                unsigned off = (warpM + mf * 16 + (lid & 15)) * 80 + ks * 32 + (lid >> 4) * 16;
                ldsm4(aH[mf], sA_H + off);
                ldsm4(aL[mf], sA_L + off);
            }
#pragma unroll
            for (int nf2 = 0; nf2 < 4; nf2++) {
                unsigned off = (warpN + nf2 * 16 + (lid & 7) + ((lid >> 4) & 1) * 8) * 80 +
                               ks * 32 + ((lid >> 3) & 1) * 16;
                unsigned rH[4], rL[4];
                ldsm4(rH, sB_H + off);
                ldsm4(rL, sB_L + off);
#pragma unroll
                for (int mf = 0; mf < 2; mf++) {
                    MMA16816(cacc[mf][2 * nf2],     aH[mf], rH[0], rH[1]);
                    MMA16816(cacc[mf][2 * nf2],     aH[mf], rL[0], rL[1]);
                    MMA16816(cacc[mf][2 * nf2],     aL[mf], rH[0], rH[1]);
                    MMA16816(cacc[mf][2 * nf2 + 1], aH[mf], rH[2], rH[3]);
                    MMA16816(cacc[mf][2 * nf2 + 1], aH[mf], rL[2], rL[3]);
                    MMA16816(cacc[mf][2 * nf2 + 1], aL[mf], rH[2], rH[3]);
                }
            }
        }
        __syncthreads();
        int ktn = kt + 2;
        if (ktn < KT) {
            size_t k0 = kbase + (size_t)ktn * 32;
#pragma unroll
            for (int i = 0; i < 8; i++) CP_ASYNC16(sdst[i] + st * STAGE_B, gsrc[i] + k0);
        }
        CP_COMMIT();
    }

    int grp = lid >> 2, qd = lid & 3;
    if (MODE == 1) {
        const float* bv = b1 + (size_t)e * 10240;
#pragma unroll
        for (int mf = 0; mf < 2; mf++) {
#pragma unroll
            for (int half = 0; half < 2; half++) {
                int n = m0 + warpM + mf * 16 + grp + half * 8;
                size_t ob = (size_t)n * 20480 + (size_t)e * 5120;
#pragma unroll
                for (int nf = 0; nf < 8; nf++) {
                    int h = h0 + (warpN >> 1) + nf * 4 + qd;
                    float val  = cacc[mf][nf][half * 2 + 0];
                    float gate = cacc[mf][nf][half * 2 + 1];
                    float v = val + bv[h];
                    float g = gate + bv[5120 + h];
                    float hid = v * (0.5f * g * (1.f + erff(g * 0.70710678118654752f)));
                    __nv_bfloat16 hh = __float2bfloat16_rn(hid);
                    g_hh[ob + h] = hh;
                    g_hl[ob + h] = __float2bfloat16_rn(hid - __bfloat162float(hh));
                }
            }
        }
    } else {
        size_t zb = (size_t)z * 1310720;
#pragma unroll
        for (int mf = 0; mf < 2; mf++) {
#pragma unroll
            for (int half = 0; half < 2; half++) {
                int n = m0 + warpM + mf * 16 + grp + half * 8;
                size_t rb = zb + (size_t)n * 1280;
#pragma unroll
                for (int nf = 0; nf < 8; nf++) {
                    int col = n0 + warpN + nf * 8 + qd * 2;
                    g_part[rb + col]     = cacc[mf][nf][half * 2 + 0];
                    g_part[rb + col + 1] = cacc[mf][nf][half * 2 + 1];
                }
            }
        }
    }
}

// ================= reduce: sum splits, gate-weight experts, add bias =================
__global__ void reduce_kernel(const float* __restrict__ b2, float* __restrict__ out) {
    int i = blockIdx.x * 256 + threadIdx.x;
    int n = i / 1280, j = i - n * 1280;
    const float* gw = g_gw + n * 4;
    float s = 0.f;
#pragma unroll
    for (int e = 0; e < 4; e++) {
        size_t base = (size_t)e * 4 * 1310720 + i;
        float p = g_part[base] + g_part[base + 1310720] +
                  g_part[base + 2621440] + g_part[base + 3932160];
        s += gw[e] * (p + b2[e * 1280 + j]);
    }
    out[i] = s;
}

// ================= launch =================
extern "C" void kernel_launch(void* const* d_in, const int* in_sizes, int n_in,
                              void* d_out, int out_size) {
    const float* x    = (const float*)d_in[0];
    const float* mask = (const float*)d_in[1];
    const float* c1w  = (const float*)d_in[2];
    const float* c1b  = (const float*)d_in[3];
    const float* bn1g = (const float*)d_in[4];
    const float* bn1b = (const float*)d_in[5];
    const float* bn1m = (const float*)d_in[6];
    const float* bn1v = (const float*)d_in[7];
    const float* c2w  = (const float*)d_in[8];
    const float* c2b  = (const float*)d_in[9];
    const float* bn2g = (const float*)d_in[10];
    const float* bn2b = (const float*)d_in[11];
    const float* bn2m = (const float*)d_in[12];
    const float* bn2v = (const float*)d_in[13];
    const float* c3w  = (const float*)d_in[14];
    const float* c3b  = (const float*)d_in[15];
    const float* bn3g = (const float*)d_in[16];
    const float* bn3b = (const float*)d_in[17];
    const float* bn3m = (const float*)d_in[18];
    const float* bn3v = (const float*)d_in[19];
    const float* fcw  = (const float*)d_in[20];
    const float* fcb  = (const float*)d_in[21];
    const float* w1   = (const float*)d_in[22];
    const float* b1   = (const float*)d_in[23];
    const float* w2   = (const float*)d_in[24];
    const float* b2   = (const float*)d_in[25];
    float* out = (float*)d_out;

    cudaFuncSetAttribute(mma_gemm_kernel<1>, cudaFuncAttributeMaxDynamicSharedMemorySize, SMEM_BYTES);
    cudaFuncSetAttribute(mma_gemm_kernel<2>, cudaFuncAttributeMaxDynamicSharedMemorySize, SMEM_BYTES);

    prep_kernel<2><<<216, 256>>>(c2w, c2b, bn2g, bn2b, bn2m, bn2v);
    prep_kernel<3><<<864, 256>>>(c3w, c3b, bn3g, bn3b, bn3m, bn3v);
    cvt_x_kernel<<<5120, 256>>>(x);
    trans_w1_kernel<<<dim3(320, 40, 4), dim3(32, 8)>>>(w1);
    trans_w2_kernel<<<dim3(40, 160, 4), dim3(32, 8)>>>(w2);
    conv1_kernel<<<dim3(1024, 8), 256>>>(mask, c1w, c1b, bn1g, bn1b, bn1m, bn1v);
    conv_gemm_kernel<2><<<dim3(256, 16, 1), 256>>>();
    conv_gemm_kernel<3><<<dim3(32, 16, 2), 256>>>();
    gate_kernel<<<1024, 128>>>(fcw, fcb);
    mma_gemm_kernel<1><<<dim3(8, 320), 256, SMEM_BYTES>>>(b1);
    mma_gemm_kernel<2><<<dim3(8, 10, 16), 256, SMEM_BYTES>>>(b1);
    reduce_kernel<<<5120, 256>>>(b2, out);
}

// round 13
// speedup vs baseline: 1.3093x; 1.1620x over previous
#include <cuda_runtime.h>
#include <cuda_fp16.h>
#include <math.h>

#define BN_EPS 1e-5f

// ================= scratch =================
__device__ float g_m1[67108864];   // conv1 out, channels-last [1024][8][16][16][32]
__device__ float g_m2[16777216];   // conv2 out, channels-last [1024][256][64]
__device__ float g_m3[4194304];    // conv3 out, channels-last [1024][32][128]
__device__ float g_wT2[55296];     // [tap27][c32][o64]
__device__ float g_shift2[64];
__device__ float g_wT3[221184];    // [tap27][c64][o128]
__device__ float g_shift3[128];
__device__ float g_gw[4096];       // [1024][4]
// fp16 split operands: A = Ah + Al (exact 22-bit split), B quantized once
__device__ __half g_xh[1310720], g_xl[1310720];   // x [1024][1280]
__device__ __half g_w1h[52428800];                // W1^T [40960][1280]
__device__ __half g_w2h[26214400];                // W2^T [1280][20480]
__device__ __half g_hh[20971520], g_hl[20971520]; // hid [1024][20480] (UNscaled)
__device__ float g_part[20971520]; // [16 = e*4+ksplit][1024][1280] partials

// ================= helpers =================
__device__ __forceinline__ unsigned smem_u32(const void* ptr) {
    unsigned a;
    asm("{ .reg .u64 t; cvta.to.shared.u64 t, %1; cvt.u32.u64 %0, t; }" : "=r"(a) : "l"(ptr));
    return a;
}
#define CP_ASYNC16(dst, src) \
    asm volatile("cp.async.cg.shared.global [%0], [%1], 16;" :: "r"(dst), "l"(src))
#define CP_COMMIT() asm volatile("cp.async.commit_group;" ::: "memory")
#define CP_WAIT1()  asm volatile("cp.async.wait_group 1;" ::: "memory")

__device__ __forceinline__ void ldsm4(unsigned* r, unsigned addr) {
    asm volatile("ldmatrix.sync.aligned.m8n8.x4.shared.b16 {%0,%1,%2,%3}, [%4];"
                 : "=r"(r[0]), "=r"(r[1]), "=r"(r[2]), "=r"(r[3]) : "r"(addr));
}
#define MMA16816(c, a, b0v, b1v) \
    asm volatile("mma.sync.aligned.m16n8k16.row.col.f32.f16.f16.f32 " \
        "{%0,%1,%2,%3}, {%4,%5,%6,%7}, {%8,%9}, {%0,%1,%2,%3};" \
        : "+f"((c)[0]), "+f"((c)[1]), "+f"((c)[2]), "+f"((c)[3]) \
        : "r"((a)[0]), "r"((a)[1]), "r"((a)[2]), "r"((a)[3]), "r"(b0v), "r"(b1v))

// ================= prep: conv weights + BN fold -> [tap][c][o] =================
template<int WHICH>
__global__ void prep_kernel(const float* __restrict__ w, const float* __restrict__ bias,
                            const float* __restrict__ bng, const float* __restrict__ bnb,
                            const float* __restrict__ bnm, const float* __restrict__ bnv) {
    constexpr int CIN  = (WHICH == 2) ? 32 : 64;
    constexpr int COUT = (WHICH == 2) ? 64 : 128;
    float* wT    = (WHICH == 2) ? g_wT2 : g_wT3;
    float* shift = (WHICH == 2) ? g_shift2 : g_shift3;
    int idx = blockIdx.x * 256 + threadIdx.x;
    const int total = CIN * 27 * COUT;
    if (idx < total) {
        int o = idx % COUT;
        int r = idx / COUT;
        int c = r % CIN;
        int tap = r / CIN;
        float s = rsqrtf(bnv[o] + BN_EPS) * bng[o];
        wT[idx] = w[((size_t)o * CIN + c) * 27 + tap] * s;
    }
    if (idx < COUT) {
        float s = rsqrtf(bnv[idx] + BN_EPS) * bng[idx];
        shift[idx] = (bias[idx] - bnm[idx]) * s + bnb[idx];
    }
}

// ================= fp16-split conversion =================
__global__ void cvt_x_kernel(const float* __restrict__ x) {
    int i = blockIdx.x * 256 + threadIdx.x;
    if (i < 1310720) {
        float v = x[i];
        __half h = __float2half_rn(v);
        g_xh[i] = h;
        g_xl[i] = __float2half_rn(v - __half2float(h));
    }
}

__global__ void trans_w1_kernel(const float* __restrict__ w1) {
    __shared__ float tile[32][33];
    int e = blockIdx.z;
    int j0 = blockIdx.x * 32, d0 = blockIdx.y * 32;
    const float* W = w1 + (size_t)e * 13107200;
    int tx = threadIdx.x, ty = threadIdx.y;
#pragma unroll
    for (int r = 0; r < 32; r += 8)
        tile[ty + r][tx] = W[(size_t)(d0 + ty + r) * 10240 + j0 + tx];
    __syncthreads();
#pragma unroll
    for (int r = 0; r < 32; r += 8) {
        size_t o = (size_t)(e * 10240 + j0 + ty + r) * 1280 + d0 + tx;
        g_w1h[o] = __float2half_rn(tile[tx][ty + r]);
    }
}

__global__ void trans_w2_kernel(const float* __restrict__ w2) {
    __shared__ float tile[32][33];
    int e = blockIdx.z;
    int j0 = blockIdx.x * 32, i0 = blockIdx.y * 32;
    const float* W = w2 + (size_t)e * 6553600;
    int tx = threadIdx.x, ty = threadIdx.y;
#pragma unroll
    for (int r = 0; r < 32; r += 8)
        tile[ty + r][tx] = W[(size_t)(i0 + ty + r) * 1280 + j0 + tx];
    __syncthreads();
#pragma unroll
    for (int r = 0; r < 32; r += 8) {
        size_t o = (size_t)(j0 + ty + r) * 20480 + e * 5120 + i0 + tx;
        g_w2h[o] = __float2half_rn(tile[tx][ty + r]);
    }
}

// ================= conv1: channels-last output =================
__global__ void conv1_kernel(const float* __restrict__ mask,
                             const float* __restrict__ w, const float* __restrict__ bias,
                             const float* __restrict__ bng, const float* __restrict__ bnb,
                             const float* __restrict__ bnm, const float* __restrict__ bnv) {
    __shared__ float ws[32][27];
    __shared__ float sscale[32], sshift[32];
    int t = threadIdx.x;
    if (t < 32) {
        float s = rsqrtf(bnv[t] + BN_EPS) * bng[t];
        sscale[t] = s;
        sshift[t] = (bias[t] - bnm[t]) * s + bnb[t];
    }
    __syncthreads();
    for (int idx = t; idx < 864; idx += 256) {
        int o = idx / 27, tap = idx % 27;
        ws[o][tap] = w[idx] * sscale[o];
    }
    __syncthreads();

    int b = blockIdx.x, d = blockIdx.y;
    int h = t >> 4, wq = t & 15;
    const float* mb = mask + (size_t)b * 16384;

    float v[27];
#pragma unroll
    for (int kd = 0; kd < 3; kd++)
#pragma unroll
        for (int kh = 0; kh < 3; kh++)
#pragma unroll
            for (int kw = 0; kw < 3; kw++) {
                int zd = 2 * d - 1 + kd, zh = 2 * h - 1 + kh, zw = 2 * wq - 1 + kw;
                bool ok = (unsigned)zd < 16u && (unsigned)zh < 32u && (unsigned)zw < 32u;
                v[(kd * 3 + kh) * 3 + kw] = ok ? mb[zd * 1024 + zh * 32 + zw] : 0.f;
            }

    float o32[32];
#pragma unroll
    for (int o = 0; o < 32; o++) {
        float acc = 0.f;
#pragma unroll
        for (int tap = 0; tap < 27; tap++) acc = fmaf(ws[o][tap], v[tap], acc);
        o32[o] = fmaxf(acc + sshift[o], 0.f);
    }
    float* op = g_m1 + ((((size_t)b * 8 + d) * 256) + t) * 32;
#pragma unroll
    for (int q = 0; q < 8; q++)
        *(float4*)(op + q * 4) = make_float4(o32[q * 4], o32[q * 4 + 1],
                                             o32[q * 4 + 2], o32[q * 4 + 3]);
}

// ================= conv2/3 channels-last implicit GEMM =================
template<int WHICH>
__global__ void conv_gemm_kernel() {
    constexpr int CIN  = (WHICH == 2) ? 32 : 64;
    constexpr int COUT = (WHICH == 2) ? 64 : 128;
    constexpr int DIN  = (WHICH == 2) ? 8 : 4;
    constexpr int HIN  = (WHICH == 2) ? 16 : 8;
    constexpr int WIN  = (WHICH == 2) ? 16 : 8;
    constexpr int HOUT = (WHICH == 2) ? 8 : 4;
    constexpr int WOUT = (WHICH == 2) ? 8 : 4;
    constexpr int DHW  = DIN * HIN * WIN;
    constexpr int POS  = ((WHICH == 2) ? 4 : 2) * HOUT * WOUT;
    constexpr int CINQ = CIN / 4;

    const float* in    = (WHICH == 2) ? g_m1 : g_m2;
    const float* wT    = (WHICH == 2) ? g_wT2 : g_wT3;
    const float* shift = (WHICH == 2) ? g_shift2 : g_shift3;
    float*       out   = (WHICH == 2) ? g_m2 : g_m3;

    __shared__ float As[CIN][68];
    __shared__ float Bs[CIN][68];
    __shared__ int   offs[27];

    int pos = blockIdx.x;
    int t = threadIdx.x;
    if (t < 27) {
        int d = pos / (HOUT * WOUT);
        int rem = pos % (HOUT * WOUT);
        int h = rem / WOUT, w = rem % WOUT;
        int kd = t / 9, r = t % 9, kh = r / 3, kw = r % 3;
        int zd = 2 * d - 1 + kd, zh = 2 * h - 1 + kh, zw = 2 * w - 1 + kw;
        bool ok = (unsigned)zd < (unsigned)DIN && (unsigned)zh < (unsigned)HIN &&
                  (unsigned)zw < (unsigned)WIN;
        offs[t] = ok ? ((zd * HIN + zh) * WIN + zw) : -1;
    }
    __syncthreads();

    int b0 = blockIdx.y * 64;
    int o0 = blockIdx.z * 64;
    int tx = t & 15, ty = t >> 4;
    float acc[4][4] = {};

    for (int tap = 0; tap < 27; tap++) {
        int off = offs[tap];
        if (off < 0) continue;
        __syncthreads();
        const float* ibase = in + (size_t)off * CIN;
#pragma unroll
        for (int i = 0; i < CINQ / 4; i++) {
            int idx = t + 256 * i;
            int bb = idx / CINQ, c4 = idx % CINQ;
            float4 v = *(const float4*)(ibase + (size_t)(b0 + bb) * (DHW * CIN) + c4 * 4);
            As[c4 * 4 + 0][bb] = v.x;
            As[c4 * 4 + 1][bb] = v.y;
            As[c4 * 4 + 2][bb] = v.z;
            As[c4 * 4 + 3][bb] = v.w;
        }
        const float* wb = wT + (size_t)tap * CIN * COUT + o0;
#pragma unroll
        for (int i = 0; i < CINQ / 4; i++) {
            int idx = t + 256 * i;
            int c = idx / 16, o4 = idx % 16;
            *(float4*)&Bs[c][o4 * 4] = *(const float4*)(wb + (size_t)c * COUT + o4 * 4);
        }
        __syncthreads();
#pragma unroll
        for (int k = 0; k < CIN; k++) {
            float4 a4 = *(const float4*)&As[k][ty * 4];
            float4 b4 = *(const float4*)&Bs[k][tx * 4];
            float a[4] = {a4.x, a4.y, a4.z, a4.w};
            float b[4] = {b4.x, b4.y, b4.z, b4.w};
#pragma unroll
            for (int i = 0; i < 4; i++)
#pragma unroll
                for (int j = 0; j < 4; j++)
                    acc[i][j] = fmaf(a[i], b[j], acc[i][j]);
        }
    }

#pragma unroll
    for (int i = 0; i < 4; i++) {
        int b = b0 + ty * 4 + i;
        float* op = out + ((size_t)b * POS + pos) * COUT + o0 + tx * 4;
        float4 v;
        v.x = fmaxf(acc[i][0] + shift[o0 + tx * 4 + 0], 0.f);
        v.y = fmaxf(acc[i][1] + shift[o0 + tx * 4 + 1], 0.f);
        v.z = fmaxf(acc[i][2] + shift[o0 + tx * 4 + 2], 0.f);
        v.w = fmaxf(acc[i][3] + shift[o0 + tx * 4 + 3], 0.f);
        *(float4*)op = v;
    }
}

// ================= gate =================
__global__ void gate_kernel(const float* __restrict__ fc_w, const float* __restrict__ fc_b) {
    int b = blockIdx.x, t = threadIdx.x;
    __shared__ float pooled[128];
    __shared__ float logit[4];
    const float* p = g_m3 + (size_t)b * 4096 + t;
    float s = 0.f;
#pragma unroll
    for (int i = 0; i < 32; i++) s += p[i * 128];
    pooled[t] = s * (1.0f / 32.0f);
    __syncthreads();
    if (t < 4) {
        float l = fc_b[t];
        const float* wrow = fc_w + t * 128;
        for (int c = 0; c < 128; c++) l = fmaf(pooled[c], wrow[c], l);
        logit[t] = l;
    }
    __syncthreads();
    if (t == 0) {
        float mx = fmaxf(fmaxf(logit[0], logit[1]), fmaxf(logit[2], logit[3]));
        float e0 = expf(logit[0] - mx), e1 = expf(logit[1] - mx);
        float e2 = expf(logit[2] - mx), e3 = expf(logit[3] - mx);
        float inv = 1.f / (e0 + e1 + e2 + e3);
        g_gw[b * 4 + 0] = e0 * inv;
        g_gw[b * 4 + 1] = e1 * inv;
        g_gw[b * 4 + 2] = e2 * inv;
        g_gw[b * 4 + 3] = e3 * inv;
    }
}

// ================= mma.sync GEMM, fp16 2-pass, 2-stage kT=32 =================
// D = Ah*Bh + Al*Bh (A exact fp16 split, B quantized once -> err ~1.4e-4)
// MODE 1 = GEGLU (hid UNscaled), MODE 2 = per-expert output GEMM with split-K x4
#define TILE_B   10240    // 128 rows * 80B
#define STAGE_B  30720    // 3 tiles: A_H, A_L, B_H
#define SMEM_BYTES 61440  // 2 stages

template<int MODE>
__global__ void __launch_bounds__(256, 2) mma_gemm_kernel(const float* __restrict__ b1) {
    extern __shared__ char smem[];
    unsigned sb = smem_u32(smem);
    int t = threadIdx.x, wid = t >> 5, lid = t & 31;

    constexpr int KT = 40;  // MODE1: 1280 K; MODE2: 1280 K per split

    int m0 = blockIdx.x * 128;
    int e = 0, h0 = 0, n0 = 0, z = 0;
    size_t kbase = 0;
    if (MODE == 1) { e = blockIdx.y / 80; h0 = (blockIdx.y % 80) * 64; }
    else {
        n0 = blockIdx.y * 128;
        z = blockIdx.z;                 // 0..15 = e*4 + ksplit
        kbase = (size_t)(z >> 2) * 5120 + (size_t)(z & 3) * 1280;
    }

    // per-thread cp.async slots: 3 tiles * 512 chunks / 256 threads = 6 each
    const __half* gsrc[6];
    unsigned sdst[6];
#pragma unroll
    for (int i = 0; i < 6; i++) {
        int c = t + 256 * i;
        int tile = c >> 9, rs = c & 511, row = rs >> 2, seg = rs & 3;
        const __half* base;
        size_t grow;
        if (MODE == 1) {
            if (tile < 2) {
                base = tile ? g_xl : g_xh;
                grow = (size_t)(m0 + row) * 1280;
            } else {
                int g = e * 10240 + (row & 1) * 5120 + h0 + (row >> 1);
                base = g_w1h;
                grow = (size_t)g * 1280;
            }
        } else {
            if (tile < 2) {
                base = tile ? g_hl : g_hh;
                grow = (size_t)(m0 + row) * 20480;
            } else {
                base = g_w2h;
                grow = (size_t)(n0 + row) * 20480;
            }
        }
        gsrc[i] = base + grow + seg * 8;
        sdst[i] = sb + tile * TILE_B + row * 80 + seg * 16;
    }

#pragma unroll
    for (int st = 0; st < 2; st++) {
        size_t k0 = kbase + st * 32;
#pragma unroll
        for (int i = 0; i < 6; i++) CP_ASYNC16(sdst[i] + st * STAGE_B, gsrc[i] + k0);
        CP_COMMIT();
    }

    float cacc[2][8][4];
#pragma unroll
    for (int mf = 0; mf < 2; mf++)
#pragma unroll
        for (int nf = 0; nf < 8; nf++)
#pragma unroll
            for (int q = 0; q < 4; q++) cacc[mf][nf][q] = 0.f;

    unsigned warpM = (wid & 3) * 32;
    unsigned warpN = (wid >> 2) * 64;

    for (int kt = 0; kt < KT; kt++) {
        CP_WAIT1();
        __syncthreads();
        int st = kt & 1;
        unsigned sA_H = sb + st * STAGE_B;
        unsigned sA_L = sA_H + TILE_B;
        unsigned sB_H = sA_H + 2 * TILE_B;

#pragma unroll
        for (int ks = 0; ks < 2; ks++) {
            unsigned aH[2][4], aL[2][4];
#pragma unroll
            for (int mf = 0; mf < 2; mf++) {
                unsigned off = (warpM + mf * 16 + (lid & 15)) * 80 + ks * 32 + (lid >> 4) * 16;
                ldsm4(aH[mf], sA_H + off);
                ldsm4(aL[mf], sA_L + off);
            }
#pragma unroll
            for (int nf2 = 0; nf2 < 4; nf2++) {
                unsigned off = (warpN + nf2 * 16 + (lid & 7) + ((lid >> 4) & 1) * 8) * 80 +
                               ks * 32 + ((lid >> 3) & 1) * 16;
                unsigned rH[4];
                ldsm4(rH, sB_H + off);
#pragma unroll
                for (int mf = 0; mf < 2; mf++) {
                    MMA16816(cacc[mf][2 * nf2],     aH[mf], rH[0], rH[1]);
                    MMA16816(cacc[mf][2 * nf2],     aL[mf], rH[0], rH[1]);
                    MMA16816(cacc[mf][2 * nf2 + 1], aH[mf], rH[2], rH[3]);
                    MMA16816(cacc[mf][2 * nf2 + 1], aL[mf], rH[2], rH[3]);
                }
            }
        }
        __syncthreads();
        int ktn = kt + 2;
        if (ktn < KT) {
            size_t k0 = kbase + (size_t)ktn * 32;
#pragma unroll
            for (int i = 0; i < 6; i++) CP_ASYNC16(sdst[i] + st * STAGE_B, gsrc[i] + k0);
        }
        CP_COMMIT();
    }

    int grp = lid >> 2, qd = lid & 3;
    if (MODE == 1) {
        const float* bv = b1 + (size_t)e * 10240;
#pragma unroll
        for (int mf = 0; mf < 2; mf++) {
#pragma unroll
            for (int half = 0; half < 2; half++) {
                int n = m0 + warpM + mf * 16 + grp + half * 8;
                size_t ob = (size_t)n * 20480 + (size_t)e * 5120;
#pragma unroll
                for (int nf = 0; nf < 8; nf++) {
                    int h = h0 + (warpN >> 1) + nf * 4 + qd;
                    float val  = cacc[mf][nf][half * 2 + 0];
                    float gate = cacc[mf][nf][half * 2 + 1];
                    float v = val + bv[h];
                    float g = gate + bv[5120 + h];
                    float hid = v * (0.5f * g * (1.f + erff(g * 0.70710678118654752f)));
                    __half hh = __float2half_rn(hid);
                    g_hh[ob + h] = hh;
                    g_hl[ob + h] = __float2half_rn(hid - __half2float(hh));
                }
            }
        }
    } else {
        size_t zb = (size_t)z * 1310720;
#pragma unroll
        for (int mf = 0; mf < 2; mf++) {
#pragma unroll
            for (int half = 0; half < 2; half++) {
                int n = m0 + warpM + mf * 16 + grp + half * 8;
                size_t rb = zb + (size_t)n * 1280;
#pragma unroll
                for (int nf = 0; nf < 8; nf++) {
                    int col = n0 + warpN + nf * 8 + qd * 2;
                    g_part[rb + col]     = cacc[mf][nf][half * 2 + 0];
                    g_part[rb + col + 1] = cacc[mf][nf][half * 2 + 1];
                }
            }
        }
    }
}

// ================= reduce: sum splits, gate-weight experts, add bias =================
__global__ void reduce_kernel(const float* __restrict__ b2, float* __restrict__ out) {
    int i = blockIdx.x * 256 + threadIdx.x;
    int n = i / 1280, j = i - n * 1280;
    const float* gw = g_gw + n * 4;
    float s = 0.f;
#pragma unroll
    for (int e = 0; e < 4; e++) {
        size_t base = (size_t)e * 4 * 1310720 + i;
        float p = g_part[base] + g_part[base + 1310720] +
                  g_part[base + 2621440] + g_part[base + 3932160];
        s += gw[e] * (p + b2[e * 1280 + j]);
    }
    out[i] = s;
}

// ================= launch =================
extern "C" void kernel_launch(void* const* d_in, const int* in_sizes, int n_in,
                              void* d_out, int out_size) {
    const float* x    = (const float*)d_in[0];
    const float* mask = (const float*)d_in[1];
    const float* c1w  = (const float*)d_in[2];
    const float* c1b  = (const float*)d_in[3];
    const float* bn1g = (const float*)d_in[4];
    const float* bn1b = (const float*)d_in[5];
    const float* bn1m = (const float*)d_in[6];
    const float* bn1v = (const float*)d_in[7];
    const float* c2w  = (const float*)d_in[8];
    const float* c2b  = (const float*)d_in[9];
    const float* bn2g = (const float*)d_in[10];
    const float* bn2b = (const float*)d_in[11];
    const float* bn2m = (const float*)d_in[12];
    const float* bn2v = (const float*)d_in[13];
    const float* c3w  = (const float*)d_in[14];
    const float* c3b  = (const float*)d_in[15];
    const float* bn3g = (const float*)d_in[16];
    const float* bn3b = (const float*)d_in[17];
    const float* bn3m = (const float*)d_in[18];
    const float* bn3v = (const float*)d_in[19];
    const float* fcw  = (const float*)d_in[20];
    const float* fcb  = (const float*)d_in[21];
    const float* w1   = (const float*)d_in[22];
    const float* b1   = (const float*)d_in[23];
    const float* w2   = (const float*)d_in[24];
    const float* b2   = (const float*)d_in[25];
    float* out = (float*)d_out;

    cudaFuncSetAttribute(mma_gemm_kernel<1>, cudaFuncAttributeMaxDynamicSharedMemorySize, SMEM_BYTES);
    cudaFuncSetAttribute(mma_gemm_kernel<2>, cudaFuncAttributeMaxDynamicSharedMemorySize, SMEM_BYTES);

    prep_kernel<2><<<216, 256>>>(c2w, c2b, bn2g, bn2b, bn2m, bn2v);
    prep_kernel<3><<<864, 256>>>(c3w, c3b, bn3g, bn3b, bn3m, bn3v);
    cvt_x_kernel<<<5120, 256>>>(x);
    trans_w1_kernel<<<dim3(320, 40, 4), dim3(32, 8)>>>(w1);
    trans_w2_kernel<<<dim3(40, 160, 4), dim3(32, 8)>>>(w2);
    conv1_kernel<<<dim3(1024, 8), 256>>>(mask, c1w, c1b, bn1g, bn1b, bn1m, bn1v);
    conv_gemm_kernel<2><<<dim3(256, 16, 1), 256>>>();
    conv_gemm_kernel<3><<<dim3(32, 16, 2), 256>>>();
    gate_kernel<<<1024, 128>>>(fcw, fcb);
    mma_gemm_kernel<1><<<dim3(8, 320), 256, SMEM_BYTES>>>(b1);
    mma_gemm_kernel<2><<<dim3(8, 10, 16), 256, SMEM_BYTES>>>(b1);
    reduce_kernel<<<5120, 256>>>(b2, out);
}

// round 14
// speedup vs baseline: 1.4644x; 1.1184x over previous
#include <cuda_runtime.h>
#include <cuda_fp16.h>
#include <math.h>

#define BN_EPS 1e-5f

// ================= scratch =================
__device__ __half g_m1[67108864]; // conv1 out, channels-last fp16 [1024][8][16][16][32]
__device__ __half g_m2[16777216]; // conv2 out, channels-last fp16 [1024][256][64]
__device__ float g_m3[4194304];   // conv3 out, channels-last [1024][32][128]
__device__ float g_wT2[55296];    // [tap27][c32][o64]
__device__ float g_shift2[64];
__device__ float g_wT3[221184];   // [tap27][c64][o128]
__device__ float g_shift3[128];
__device__ float g_gw[4096];      // [1024][4]
// fp16 operands: x exact-split (xh+xl); W1/W2/hid singly quantized
__device__ __half g_xh[1310720], g_xl[1310720];   // x [1024][1280]
__device__ __half g_w1h[52428800];                // W1^T [40960][1280]
__device__ __half g_w2h[26214400];                // W2^T [1280][20480]
__device__ __half g_hh[20971520];                 // hid [1024][20480] (UNscaled)
__device__ float g_part[20971520]; // [16 = e*4+ksplit][1024][1280] partials

// ================= helpers =================
__device__ __forceinline__ unsigned smem_u32(const void* ptr) {
    unsigned a;
    asm("{ .reg .u64 t; cvta.to.shared.u64 t, %1; cvt.u32.u64 %0, t; }" : "=r"(a) : "l"(ptr));
    return a;
}
#define CP_ASYNC16(dst, src) \
    asm volatile("cp.async.cg.shared.global [%0], [%1], 16;" :: "r"(dst), "l"(src))
#define CP_COMMIT() asm volatile("cp.async.commit_group;" ::: "memory")
#define CP_WAIT1()  asm volatile("cp.async.wait_group 1;" ::: "memory")

__device__ __forceinline__ void ldsm4(unsigned* r, unsigned addr) {
    asm volatile("ldmatrix.sync.aligned.m8n8.x4.shared.b16 {%0,%1,%2,%3}, [%4];"
                 : "=r"(r[0]), "=r"(r[1]), "=r"(r[2]), "=r"(r[3]) : "r"(addr));
}
#define MMA16816(c, a, b0v, b1v) \
    asm volatile("mma.sync.aligned.m16n8k16.row.col.f32.f16.f16.f32 " \
        "{%0,%1,%2,%3}, {%4,%5,%6,%7}, {%8,%9}, {%0,%1,%2,%3};" \
        : "+f"((c)[0]), "+f"((c)[1]), "+f"((c)[2]), "+f"((c)[3]) \
        : "r"((a)[0]), "r"((a)[1]), "r"((a)[2]), "r"((a)[3]), "r"(b0v), "r"(b1v))

// ================= prep: conv weights + BN fold -> [tap][c][o] =================
template<int WHICH>
__global__ void prep_kernel(const float* __restrict__ w, const float* __restrict__ bias,
                            const float* __restrict__ bng, const float* __restrict__ bnb,
                            const float* __restrict__ bnm, const float* __restrict__ bnv) {
    constexpr int CIN  = (WHICH == 2) ? 32 : 64;
    constexpr int COUT = (WHICH == 2) ? 64 : 128;
    float* wT    = (WHICH == 2) ? g_wT2 : g_wT3;
    float* shift = (WHICH == 2) ? g_shift2 : g_shift3;
    int idx = blockIdx.x * 256 + threadIdx.x;
    const int total = CIN * 27 * COUT;
    if (idx < total) {
        int o = idx % COUT;
        int r = idx / COUT;
        int c = r % CIN;
        int tap = r / CIN;
        float s = rsqrtf(bnv[o] + BN_EPS) * bng[o];
        wT[idx] = w[((size_t)o * CIN + c) * 27 + tap] * s;
    }
    if (idx < COUT) {
        float s = rsqrtf(bnv[idx] + BN_EPS) * bng[idx];
        shift[idx] = (bias[idx] - bnm[idx]) * s + bnb[idx];
    }
}

// ================= fp16-split conversion =================
__global__ void cvt_x_kernel(const float* __restrict__ x) {
    int i = blockIdx.x * 256 + threadIdx.x;
    if (i < 1310720) {
        float v = x[i];
        __half h = __float2half_rn(v);
        g_xh[i] = h;
        g_xl[i] = __float2half_rn(v - __half2float(h));
    }
}

__global__ void trans_w1_kernel(const float* __restrict__ w1) {
    __shared__ float tile[32][33];
    int e = blockIdx.z;
    int j0 = blockIdx.x * 32, d0 = blockIdx.y * 32;
    const float* W = w1 + (size_t)e * 13107200;
    int tx = threadIdx.x, ty = threadIdx.y;
#pragma unroll
    for (int r = 0; r < 32; r += 8)
        tile[ty + r][tx] = W[(size_t)(d0 + ty + r) * 10240 + j0 + tx];
    __syncthreads();
#pragma unroll
    for (int r = 0; r < 32; r += 8) {
        size_t o = (size_t)(e * 10240 + j0 + ty + r) * 1280 + d0 + tx;
        g_w1h[o] = __float2half_rn(tile[tx][ty + r]);
    }
}

__global__ void trans_w2_kernel(const float* __restrict__ w2) {
    __shared__ float tile[32][33];
    int e = blockIdx.z;
    int j0 = blockIdx.x * 32, i0 = blockIdx.y * 32;
    const float* W = w2 + (size_t)e * 6553600;
    int tx = threadIdx.x, ty = threadIdx.y;
#pragma unroll
    for (int r = 0; r < 32; r += 8)
        tile[ty + r][tx] = W[(size_t)(i0 + ty + r) * 1280 + j0 + tx];
    __syncthreads();
#pragma unroll
    for (int r = 0; r < 32; r += 8) {
        size_t o = (size_t)(j0 + ty + r) * 20480 + e * 5120 + i0 + tx;
        g_w2h[o] = __float2half_rn(tile[tx][ty + r]);
    }
}

// ================= conv1: channels-last fp16 output =================
__global__ void conv1_kernel(const float* __restrict__ mask,
                             const float* __restrict__ w, const float* __restrict__ bias,
                             const float* __restrict__ bng, const float* __restrict__ bnb,
                             const float* __restrict__ bnm, const float* __restrict__ bnv) {
    __shared__ float ws[32][27];
    __shared__ float sscale[32], sshift[32];
    int t = threadIdx.x;
    if (t < 32) {
        float s = rsqrtf(bnv[t] + BN_EPS) * bng[t];
        sscale[t] = s;
        sshift[t] = (bias[t] - bnm[t]) * s + bnb[t];
    }
    __syncthreads();
    for (int idx = t; idx < 864; idx += 256) {
        int o = idx / 27, tap = idx % 27;
        ws[o][tap] = w[idx] * sscale[o];
    }
    __syncthreads();

    int b = blockIdx.x, d = blockIdx.y;
    int h = t >> 4, wq = t & 15;
    const float* mb = mask + (size_t)b * 16384;

    float v[27];
#pragma unroll
    for (int kd = 0; kd < 3; kd++)
#pragma unroll
        for (int kh = 0; kh < 3; kh++)
#pragma unroll
            for (int kw = 0; kw < 3; kw++) {
                int zd = 2 * d - 1 + kd, zh = 2 * h - 1 + kh, zw = 2 * wq - 1 + kw;
                bool ok = (unsigned)zd < 16u && (unsigned)zh < 32u && (unsigned)zw < 32u;
                v[(kd * 3 + kh) * 3 + kw] = ok ? mb[zd * 1024 + zh * 32 + zw] : 0.f;
            }

    __half2 o16[16];
#pragma unroll
    for (int o = 0; o < 16; o++) {
        float a0 = 0.f, a1 = 0.f;
#pragma unroll
        for (int tap = 0; tap < 27; tap++) {
            a0 = fmaf(ws[2 * o][tap], v[tap], a0);
            a1 = fmaf(ws[2 * o + 1][tap], v[tap], a1);
        }
        o16[o] = __floats2half2_rn(fmaxf(a0 + sshift[2 * o], 0.f),
                                   fmaxf(a1 + sshift[2 * o + 1], 0.f));
    }
    __half* op = g_m1 + ((((size_t)b * 8 + d) * 256) + t) * 32;
#pragma unroll
    for (int q = 0; q < 4; q++)
        *(uint4*)(op + q * 8) = ((uint4*)o16)[q];
}

// ================= conv2/3 channels-last implicit GEMM (fp16 in) =================
template<int WHICH>
__global__ void conv_gemm_kernel() {
    constexpr int CIN  = (WHICH == 2) ? 32 : 64;
    constexpr int COUT = (WHICH == 2) ? 64 : 128;
    constexpr int DIN  = (WHICH == 2) ? 8 : 4;
    constexpr int HIN  = (WHICH == 2) ? 16 : 8;
    constexpr int WIN  = (WHICH == 2) ? 16 : 8;
    constexpr int HOUT = (WHICH == 2) ? 8 : 4;
    constexpr int WOUT = (WHICH == 2) ? 8 : 4;
    constexpr int DHW  = DIN * HIN * WIN;
    constexpr int POS  = ((WHICH == 2) ? 4 : 2) * HOUT * WOUT;
    constexpr int CH   = CIN / 8;   // 16B chunks per row

    const __half* in   = (WHICH == 2) ? g_m1 : g_m2;
    const float* wT    = (WHICH == 2) ? g_wT2 : g_wT3;
    const float* shift = (WHICH == 2) ? g_shift2 : g_shift3;

    __shared__ float As[CIN][68];
    __shared__ float Bs[CIN][68];
    __shared__ int   offs[27];

    int pos = blockIdx.x;
    int t = threadIdx.x;
    if (t < 27) {
        int d = pos / (HOUT * WOUT);
        int rem = pos % (HOUT * WOUT);
        int h = rem / WOUT, w = rem % WOUT;
        int kd = t / 9, r = t % 9, kh = r / 3, kw = r % 3;
        int zd = 2 * d - 1 + kd, zh = 2 * h - 1 + kh, zw = 2 * w - 1 + kw;
        bool ok = (unsigned)zd < (unsigned)DIN && (unsigned)zh < (unsigned)HIN &&
                  (unsigned)zw < (unsigned)WIN;
        offs[t] = ok ? ((zd * HIN + zh) * WIN + zw) : -1;
    }
    __syncthreads();

    int b0 = blockIdx.y * 64;
    int o0 = blockIdx.z * 64;
    int tx = t & 15, ty = t >> 4;
    float acc[4][4] = {};

    for (int tap = 0; tap < 27; tap++) {
        int off = offs[tap];
        if (off < 0) continue;
        __syncthreads();
        const __half* ibase = in + (size_t)off * CIN;
#pragma unroll
        for (int i = 0; i < (64 * CH) / 256; i++) {  // conv2: 1, conv3: 2
            int idx = t + 256 * i;
            int bb = idx / CH, c8 = idx % CH;
            uint4 v = *(const uint4*)(ibase + (size_t)(b0 + bb) * (DHW * CIN) + c8 * 8);
            __half2* hp = (__half2*)&v;
#pragma unroll
            for (int j = 0; j < 4; j++) {
                float2 f = __half22float2(hp[j]);
                As[c8 * 8 + 2 * j + 0][bb] = f.x;
                As[c8 * 8 + 2 * j + 1][bb] = f.y;
            }
        }
        const float* wb = wT + (size_t)tap * CIN * COUT + o0;
#pragma unroll
        for (int i = 0; i < CIN / 16; i++) {
            int idx = t + 256 * i;
            int c = idx / 16, o4 = idx % 16;
            *(float4*)&Bs[c][o4 * 4] = *(const float4*)(wb + (size_t)c * COUT + o4 * 4);
        }
        __syncthreads();
#pragma unroll
        for (int k = 0; k < CIN; k++) {
            float4 a4 = *(const float4*)&As[k][ty * 4];
            float4 b4 = *(const float4*)&Bs[k][tx * 4];
            float a[4] = {a4.x, a4.y, a4.z, a4.w};
            float b[4] = {b4.x, b4.y, b4.z, b4.w};
#pragma unroll
            for (int i = 0; i < 4; i++)
#pragma unroll
                for (int j = 0; j < 4; j++)
                    acc[i][j] = fmaf(a[i], b[j], acc[i][j]);
        }
    }

#pragma unroll
    for (int i = 0; i < 4; i++) {
        int b = b0 + ty * 4 + i;
        float v0 = fmaxf(acc[i][0] + shift[o0 + tx * 4 + 0], 0.f);
        float v1 = fmaxf(acc[i][1] + shift[o0 + tx * 4 + 1], 0.f);
        float v2 = fmaxf(acc[i][2] + shift[o0 + tx * 4 + 2], 0.f);
        float v3 = fmaxf(acc[i][3] + shift[o0 + tx * 4 + 3], 0.f);
        if (WHICH == 2) {
            __half* op = g_m2 + ((size_t)b * POS + pos) * COUT + o0 + tx * 4;
            __half2 h0 = __floats2half2_rn(v0, v1);
            __half2 h1 = __floats2half2_rn(v2, v3);
            *(__half2*)op = h0;
            *(__half2*)(op + 2) = h1;
        } else {
            float* op = g_m3 + ((size_t)b * POS + pos) * COUT + o0 + tx * 4;
            *(float4*)op = make_float4(v0, v1, v2, v3);
        }
    }
}

// ================= gate =================
__global__ void gate_kernel(const float* __restrict__ fc_w, const float* __restrict__ fc_b) {
    int b = blockIdx.x, t = threadIdx.x;
    __shared__ float pooled[128];
    __shared__ float logit[4];
    const float* p = g_m3 + (size_t)b * 4096 + t;
    float s = 0.f;
#pragma unroll
    for (int i = 0; i < 32; i++) s += p[i * 128];
    pooled[t] = s * (1.0f / 32.0f);
    __syncthreads();
    if (t < 4) {
        float l = fc_b[t];
        const float* wrow = fc_w + t * 128;
        for (int c = 0; c < 128; c++) l = fmaf(pooled[c], wrow[c], l);
        logit[t] = l;
    }
    __syncthreads();
    if (t == 0) {
        float mx = fmaxf(fmaxf(logit[0], logit[1]), fmaxf(logit[2], logit[3]));
        float e0 = expf(logit[0] - mx), e1 = expf(logit[1] - mx);
        float e2 = expf(logit[2] - mx), e3 = expf(logit[3] - mx);
        float inv = 1.f / (e0 + e1 + e2 + e3);
        g_gw[b * 4 + 0] = e0 * inv;
        g_gw[b * 4 + 1] = e1 * inv;
        g_gw[b * 4 + 2] = e2 * inv;
        g_gw[b * 4 + 3] = e3 * inv;
    }
}

// ================= mma.sync GEMM, 2-stage kT=32 =================
// MODE 1: GEGLU, 2-pass A (xh+xl exact split) x W1h  -> hid (fp16, UNscaled)
// MODE 2: per-expert out GEMM, 1-pass hid_h x W2h, split-K x4 (z = e*4+ks)
#define TILE_B   10240    // 128 rows * 80B

template<int MODE>
__global__ void __launch_bounds__(256, 2) mma_gemm_kernel(const float* __restrict__ b1) {
    extern __shared__ char smem[];
    unsigned sb = smem_u32(smem);
    int t = threadIdx.x, wid = t >> 5, lid = t & 31;

    constexpr int KT = 40;
    constexpr int NTILES = (MODE == 1) ? 3 : 2;
    constexpr int NCHUNK = NTILES * 2;          // per-thread cp.async chunks
    constexpr unsigned STAGE = NTILES * TILE_B;

    int m0 = blockIdx.x * 128;
    int e = 0, h0 = 0, n0 = 0, z = 0;
    size_t kbase = 0;
    if (MODE == 1) { e = blockIdx.y / 80; h0 = (blockIdx.y % 80) * 64; }
    else {
        n0 = blockIdx.y * 128;
        z = blockIdx.z;
        kbase = (size_t)(z >> 2) * 5120 + (size_t)(z & 3) * 1280;
    }

    const __half* gsrc[NCHUNK];
    unsigned sdst[NCHUNK];
#pragma unroll
    for (int i = 0; i < NCHUNK; i++) {
        int c = t + 256 * i;
        int tile = c >> 9, rs = c & 511, row = rs >> 2, seg = rs & 3;
        const __half* base;
        size_t grow;
        if (MODE == 1) {
            if (tile < 2) {
                base = tile ? g_xl : g_xh;
                grow = (size_t)(m0 + row) * 1280;
            } else {
                int g = e * 10240 + (row & 1) * 5120 + h0 + (row >> 1);
                base = g_w1h;
                grow = (size_t)g * 1280;
            }
        } else {
            if (tile == 0) {
                base = g_hh;
                grow = (size_t)(m0 + row) * 20480;
            } else {
                base = g_w2h;
                grow = (size_t)(n0 + row) * 20480;
            }
        }
        gsrc[i] = base + grow + seg * 8;
        sdst[i] = sb + tile * TILE_B + row * 80 + seg * 16;
    }

#pragma unroll
    for (int st = 0; st < 2; st++) {
        size_t k0 = kbase + st * 32;
#pragma unroll
        for (int i = 0; i < NCHUNK; i++) CP_ASYNC16(sdst[i] + st * STAGE, gsrc[i] + k0);
        CP_COMMIT();
    }

    float cacc[2][8][4];
#pragma unroll
    for (int mf = 0; mf < 2; mf++)
#pragma unroll
        for (int nf = 0; nf < 8; nf++)
#pragma unroll
            for (int q = 0; q < 4; q++) cacc[mf][nf][q] = 0.f;

    unsigned warpM = (wid & 3) * 32;
    unsigned warpN = (wid >> 2) * 64;

    for (int kt = 0; kt < KT; kt++) {
        CP_WAIT1();
        __syncthreads();
        int st = kt & 1;
        unsigned sA_H = sb + st * STAGE;
        unsigned sA_L = sA_H + TILE_B;                       // MODE 1 only
        unsigned sB_H = sA_H + (NTILES - 1) * TILE_B;

#pragma unroll
        for (int ks = 0; ks < 2; ks++) {
            unsigned aH[2][4], aL[2][4];
#pragma unroll
            for (int mf = 0; mf < 2; mf++) {
                unsigned off = (warpM + mf * 16 + (lid & 15)) * 80 + ks * 32 + (lid >> 4) * 16;
                ldsm4(aH[mf], sA_H + off);
                if (MODE == 1) ldsm4(aL[mf], sA_L + off);
            }
#pragma unroll
            for (int nf2 = 0; nf2 < 4; nf2++) {
                unsigned off = (warpN + nf2 * 16 + (lid & 7) + ((lid >> 4) & 1) * 8) * 80 +
                               ks * 32 + ((lid >> 3) & 1) * 16;
                unsigned rH[4];
                ldsm4(rH, sB_H + off);
#pragma unroll
                for (int mf = 0; mf < 2; mf++) {
                    MMA16816(cacc[mf][2 * nf2],     aH[mf], rH[0], rH[1]);
                    MMA16816(cacc[mf][2 * nf2 + 1], aH[mf], rH[2], rH[3]);
                    if (MODE == 1) {
                        MMA16816(cacc[mf][2 * nf2],     aL[mf], rH[0], rH[1]);
                        MMA16816(cacc[mf][2 * nf2 + 1], aL[mf], rH[2], rH[3]);
                    }
                }
            }
        }
        __syncthreads();
        int ktn = kt + 2;
        if (ktn < KT) {
            size_t k0 = kbase + (size_t)ktn * 32;
#pragma unroll
            for (int i = 0; i < NCHUNK; i++) CP_ASYNC16(sdst[i] + st * STAGE, gsrc[i] + k0);
        }
        CP_COMMIT();
    }

    int grp = lid >> 2, qd = lid & 3;
    if (MODE == 1) {
        const float* bv = b1 + (size_t)e * 10240;
#pragma unroll
        for (int mf = 0; mf < 2; mf++) {
#pragma unroll
            for (int half = 0; half < 2; half++) {
                int n = m0 + warpM + mf * 16 + grp + half * 8;
                size_t ob = (size_t)n * 20480 + (size_t)e * 5120;
#pragma unroll
                for (int nf = 0; nf < 8; nf++) {
                    int h = h0 + (warpN >> 1) + nf * 4 + qd;
                    float val  = cacc[mf][nf][half * 2 + 0];
                    float gate = cacc[mf][nf][half * 2 + 1];
                    float v = val + bv[h];
                    float g = gate + bv[5120 + h];
                    float hid = v * (0.5f * g * (1.f + erff(g * 0.70710678118654752f)));
                    g_hh[ob + h] = __float2half_rn(hid);
                }
            }
        }
    } else {
        size_t zb = (size_t)z * 1310720;
#pragma unroll
        for (int mf = 0; mf < 2; mf++) {
#pragma unroll
            for (int half = 0; half < 2; half++) {
                int n = m0 + warpM + mf * 16 + grp + half * 8;
                size_t rb = zb + (size_t)n * 1280;
#pragma unroll
                for (int nf = 0; nf < 8; nf++) {
                    int col = n0 + warpN + nf * 8 + qd * 2;
                    g_part[rb + col]     = cacc[mf][nf][half * 2 + 0];
                    g_part[rb + col + 1] = cacc[mf][nf][half * 2 + 1];
                }
            }
        }
    }
}

// ================= reduce: sum splits, gate-weight experts, add bias =================
__global__ void reduce_kernel(const float* __restrict__ b2, float* __restrict__ out) {
    int i = blockIdx.x * 256 + threadIdx.x;
    int n = i / 1280, j = i - n * 1280;
    const float* gw = g_gw + n * 4;
    float s = 0.f;
#pragma unroll
    for (int e = 0; e < 4; e++) {
        size_t base = (size_t)e * 4 * 1310720 + i;
        float p = g_part[base] + g_part[base + 1310720] +
                  g_part[base + 2621440] + g_part[base + 3932160];
        s += gw[e] * (p + b2[e * 1280 + j]);
    }
    out[i] = s;
}

// ================= launch =================
extern "C" void kernel_launch(void* const* d_in, const int* in_sizes, int n_in,
                              void* d_out, int out_size) {
    const float* x    = (const float*)d_in[0];
    const float* mask = (const float*)d_in[1];
    const float* c1w  = (const float*)d_in[2];
    const float* c1b  = (const float*)d_in[3];
    const float* bn1g = (const float*)d_in[4];
    const float* bn1b = (const float*)d_in[5];
    const float* bn1m = (const float*)d_in[6];
    const float* bn1v = (const float*)d_in[7];
    const float* c2w  = (const float*)d_in[8];
    const float* c2b  = (const float*)d_in[9];
    const float* bn2g = (const float*)d_in[10];
    const float* bn2b = (const float*)d_in[11];
    const float* bn2m = (const float*)d_in[12];
    const float* bn2v = (const float*)d_in[13];
    const float* c3w  = (const float*)d_in[14];
    const float* c3b  = (const float*)d_in[15];
    const float* bn3g = (const float*)d_in[16];
    const float* bn3b = (const float*)d_in[17];
    const float* bn3m = (const float*)d_in[18];
    const float* bn3v = (const float*)d_in[19];
    const float* fcw  = (const float*)d_in[20];
    const float* fcb  = (const float*)d_in[21];
    const float* w1   = (const float*)d_in[22];
    const float* b1   = (const float*)d_in[23];
    const float* w2   = (const float*)d_in[24];
    const float* b2   = (const float*)d_in[25];
    float* out = (float*)d_out;

    cudaFuncSetAttribute(mma_gemm_kernel<1>, cudaFuncAttributeMaxDynamicSharedMemorySize, 61440);
    cudaFuncSetAttribute(mma_gemm_kernel<2>, cudaFuncAttributeMaxDynamicSharedMemorySize, 40960);

    prep_kernel<2><<<216, 256>>>(c2w, c2b, bn2g, bn2b, bn2m, bn2v);
    prep_kernel<3><<<864, 256>>>(c3w, c3b, bn3g, bn3b, bn3m, bn3v);
    cvt_x_kernel<<<5120, 256>>>(x);
    trans_w1_kernel<<<dim3(320, 40, 4), dim3(32, 8)>>>(w1);
    trans_w2_kernel<<<dim3(40, 160, 4), dim3(32, 8)>>>(w2);
    conv1_kernel<<<dim3(1024, 8), 256>>>(mask, c1w, c1b, bn1g, bn1b, bn1m, bn1v);
    conv_gemm_kernel<2><<<dim3(256, 16, 1), 256>>>();
    conv_gemm_kernel<3><<<dim3(32, 16, 2), 256>>>();
    gate_kernel<<<1024, 128>>>(fcw, fcb);
    mma_gemm_kernel<1><<<dim3(8, 320), 256, 61440>>>(b1);
    mma_gemm_kernel<2><<<dim3(8, 10, 16), 256, 40960>>>(b1);
    reduce_kernel<<<5120, 256>>>(b2, out);
}

// round 15
// speedup vs baseline: 1.6943x; 1.1570x over previous
#include <cuda_runtime.h>
#include <cuda_fp16.h>
#include <math.h>

#define BN_EPS 1e-5f

// ================= scratch =================
__device__ __half g_m1[67108864]; // conv1 out, channels-last fp16 [1024][8][16][16][32]
__device__ __half g_m2[16777216]; // conv2 out, channels-last fp16 [1024][256][64]
__device__ float g_m3[4194304];   // conv3 out, channels-last [1024][32][128]
__device__ float g_wT2[55296];    // [tap27][c32][o64]
__device__ float g_shift2[64];
__device__ float g_wT3[221184];   // [tap27][c64][o128]
__device__ float g_shift3[128];
__device__ float g_gw[4096];      // [1024][4]
// fp16 operands, all singly quantized (x, W1, W2, hid)
__device__ __half g_xh[1310720];                  // x [1024][1280]
__device__ __half g_w1h[52428800];                // W1^T [40960][1280]
__device__ __half g_w2h[26214400];                // W2^T [1280][20480]
__device__ __half g_hh[20971520];                 // hid [1024][20480] (UNscaled)
__device__ float g_part[20971520]; // [16 = e*4+ksplit][1024][1280] partials

// ================= helpers =================
__device__ __forceinline__ unsigned smem_u32(const void* ptr) {
    unsigned a;
    asm("{ .reg .u64 t; cvta.to.shared.u64 t, %1; cvt.u32.u64 %0, t; }" : "=r"(a) : "l"(ptr));
    return a;
}
#define CP_ASYNC16(dst, src) \
    asm volatile("cp.async.cg.shared.global [%0], [%1], 16;" :: "r"(dst), "l"(src))
#define CP_COMMIT() asm volatile("cp.async.commit_group;" ::: "memory")
#define CP_WAIT1()  asm volatile("cp.async.wait_group 1;" ::: "memory")

__device__ __forceinline__ void ldsm4(unsigned* r, unsigned addr) {
    asm volatile("ldmatrix.sync.aligned.m8n8.x4.shared.b16 {%0,%1,%2,%3}, [%4];"
                 : "=r"(r[0]), "=r"(r[1]), "=r"(r[2]), "=r"(r[3]) : "r"(addr));
}
#define MMA16816(c, a, b0v, b1v) \
    asm volatile("mma.sync.aligned.m16n8k16.row.col.f32.f16.f16.f32 " \
        "{%0,%1,%2,%3}, {%4,%5,%6,%7}, {%8,%9}, {%0,%1,%2,%3};" \
        : "+f"((c)[0]), "+f"((c)[1]), "+f"((c)[2]), "+f"((c)[3]) \
        : "r"((a)[0]), "r"((a)[1]), "r"((a)[2]), "r"((a)[3]), "r"(b0v), "r"(b1v))

// ================= prep: conv weights + BN fold -> [tap][c][o] =================
template<int WHICH>
__global__ void prep_kernel(const float* __restrict__ w, const float* __restrict__ bias,
                            const float* __restrict__ bng, const float* __restrict__ bnb,
                            const float* __restrict__ bnm, const float* __restrict__ bnv) {
    constexpr int CIN  = (WHICH == 2) ? 32 : 64;
    constexpr int COUT = (WHICH == 2) ? 64 : 128;
    float* wT    = (WHICH == 2) ? g_wT2 : g_wT3;
    float* shift = (WHICH == 2) ? g_shift2 : g_shift3;
    int idx = blockIdx.x * 256 + threadIdx.x;
    const int total = CIN * 27 * COUT;
    if (idx < total) {
        int o = idx % COUT;
        int r = idx / COUT;
        int c = r % CIN;
        int tap = r / CIN;
        float s = rsqrtf(bnv[o] + BN_EPS) * bng[o];
        wT[idx] = w[((size_t)o * CIN + c) * 27 + tap] * s;
    }
    if (idx < COUT) {
        float s = rsqrtf(bnv[idx] + BN_EPS) * bng[idx];
        shift[idx] = (bias[idx] - bnm[idx]) * s + bnb[idx];
    }
}

// ================= fp16 conversion =================
__global__ void cvt_x_kernel(const float* __restrict__ x) {
    int i = blockIdx.x * 256 + threadIdx.x;
    if (i < 1310720) g_xh[i] = __float2half_rn(x[i]);
}

__global__ void trans_w1_kernel(const float* __restrict__ w1) {
    __shared__ float tile[32][33];
    int e = blockIdx.z;
    int j0 = blockIdx.x * 32, d0 = blockIdx.y * 32;
    const float* W = w1 + (size_t)e * 13107200;
    int tx = threadIdx.x, ty = threadIdx.y;
#pragma unroll
    for (int r = 0; r < 32; r += 8)
        tile[ty + r][tx] = W[(size_t)(d0 + ty + r) * 10240 + j0 + tx];
    __syncthreads();
#pragma unroll
    for (int r = 0; r < 32; r += 8) {
        size_t o = (size_t)(e * 10240 + j0 + ty + r) * 1280 + d0 + tx;
        g_w1h[o] = __float2half_rn(tile[tx][ty + r]);
    }
}

__global__ void trans_w2_kernel(const float* __restrict__ w2) {
    __shared__ float tile[32][33];
    int e = blockIdx.z;
    int j0 = blockIdx.x * 32, i0 = blockIdx.y * 32;
    const float* W = w2 + (size_t)e * 6553600;
    int tx = threadIdx.x, ty = threadIdx.y;
#pragma unroll
    for (int r = 0; r < 32; r += 8)
        tile[ty + r][tx] = W[(size_t)(i0 + ty + r) * 1280 + j0 + tx];
    __syncthreads();
#pragma unroll
    for (int r = 0; r < 32; r += 8) {
        size_t o = (size_t)(j0 + ty + r) * 20480 + e * 5120 + i0 + tx;
        g_w2h[o] = __float2half_rn(tile[tx][ty + r]);
    }
}

// ================= conv1: channels-last fp16 output =================
__global__ void conv1_kernel(const float* __restrict__ mask,
                             const float* __restrict__ w, const float* __restrict__ bias,
                             const float* __restrict__ bng, const float* __restrict__ bnb,
                             const float* __restrict__ bnm, const float* __restrict__ bnv) {
    __shared__ float ws[32][27];
    __shared__ float sscale[32], sshift[32];
    int t = threadIdx.x;
    if (t < 32) {
        float s = rsqrtf(bnv[t] + BN_EPS) * bng[t];
        sscale[t] = s;
        sshift[t] = (bias[t] - bnm[t]) * s + bnb[t];
    }
    __syncthreads();
    for (int idx = t; idx < 864; idx += 256) {
        int o = idx / 27, tap = idx % 27;
        ws[o][tap] = w[idx] * sscale[o];
    }
    __syncthreads();

    int b = blockIdx.x, d = blockIdx.y;
    int h = t >> 4, wq = t & 15;
    const float* mb = mask + (size_t)b * 16384;

    float v[27];
#pragma unroll
    for (int kd = 0; kd < 3; kd++)
#pragma unroll
        for (int kh = 0; kh < 3; kh++)
#pragma unroll
            for (int kw = 0; kw < 3; kw++) {
                int zd = 2 * d - 1 + kd, zh = 2 * h - 1 + kh, zw = 2 * wq - 1 + kw;
                bool ok = (unsigned)zd < 16u && (unsigned)zh < 32u && (unsigned)zw < 32u;
                v[(kd * 3 + kh) * 3 + kw] = ok ? mb[zd * 1024 + zh * 32 + zw] : 0.f;
            }

    __half2 o16[16];
#pragma unroll
    for (int o = 0; o < 16; o++) {
        float a0 = 0.f, a1 = 0.f;
#pragma unroll
        for (int tap = 0; tap < 27; tap++) {
            a0 = fmaf(ws[2 * o][tap], v[tap], a0);
            a1 = fmaf(ws[2 * o + 1][tap], v[tap], a1);
        }
        o16[o] = __floats2half2_rn(fmaxf(a0 + sshift[2 * o], 0.f),
                                   fmaxf(a1 + sshift[2 * o + 1], 0.f));
    }
    __half* op = g_m1 + ((((size_t)b * 8 + d) * 256) + t) * 32;
#pragma unroll
    for (int q = 0; q < 4; q++)
        *(uint4*)(op + q * 8) = ((uint4*)o16)[q];
}

// ================= conv2/3 channels-last implicit GEMM (fp16 in) =================
template<int WHICH>
__global__ void conv_gemm_kernel() {
    constexpr int CIN  = (WHICH == 2) ? 32 : 64;
    constexpr int COUT = (WHICH == 2) ? 64 : 128;
    constexpr int DIN  = (WHICH == 2) ? 8 : 4;
    constexpr int HIN  = (WHICH == 2) ? 16 : 8;
    constexpr int WIN  = (WHICH == 2) ? 16 : 8;
    constexpr int HOUT = (WHICH == 2) ? 8 : 4;
    constexpr int WOUT = (WHICH == 2) ? 8 : 4;
    constexpr int DHW  = DIN * HIN * WIN;
    constexpr int POS  = ((WHICH == 2) ? 4 : 2) * HOUT * WOUT;
    constexpr int CH   = CIN / 8;   // 16B chunks per row

    const __half* in   = (WHICH == 2) ? g_m1 : g_m2;
    const float* wT    = (WHICH == 2) ? g_wT2 : g_wT3;
    const float* shift = (WHICH == 2) ? g_shift2 : g_shift3;

    __shared__ float As[CIN][68];
    __shared__ float Bs[CIN][68];
    __shared__ int   offs[27];

    int pos = blockIdx.x;
    int t = threadIdx.x;
    if (t < 27) {
        int d = pos / (HOUT * WOUT);
        int rem = pos % (HOUT * WOUT);
        int h = rem / WOUT, w = rem % WOUT;
        int kd = t / 9, r = t % 9, kh = r / 3, kw = r % 3;
        int zd = 2 * d - 1 + kd, zh = 2 * h - 1 + kh, zw = 2 * w - 1 + kw;
        bool ok = (unsigned)zd < (unsigned)DIN && (unsigned)zh < (unsigned)HIN &&
                  (unsigned)zw < (unsigned)WIN;
        offs[t] = ok ? ((zd * HIN + zh) * WIN + zw) : -1;
    }
    __syncthreads();

    int b0 = blockIdx.y * 64;
    int o0 = blockIdx.z * 64;
    int tx = t & 15, ty = t >> 4;
    float acc[4][4] = {};

    for (int tap = 0; tap < 27; tap++) {
        int off = offs[tap];
        if (off < 0) continue;
        __syncthreads();
        const __half* ibase = in + (size_t)off * CIN;
#pragma unroll
        for (int i = 0; i < (64 * CH) / 256; i++) {  // conv2: 1, conv3: 2
            int idx = t + 256 * i;
            int bb = idx / CH, c8 = idx % CH;
            uint4 v = *(const uint4*)(ibase + (size_t)(b0 + bb) * (DHW * CIN) + c8 * 8);
            __half2* hp = (__half2*)&v;
#pragma unroll
            for (int j = 0; j < 4; j++) {
                float2 f = __half22float2(hp[j]);
                As[c8 * 8 + 2 * j + 0][bb] = f.x;
                As[c8 * 8 + 2 * j + 1][bb] = f.y;
            }
        }
        const float* wb = wT + (size_t)tap * CIN * COUT + o0;
#pragma unroll
        for (int i = 0; i < CIN / 16; i++) {
            int idx = t + 256 * i;
            int c = idx / 16, o4 = idx % 16;
            *(float4*)&Bs[c][o4 * 4] = *(const float4*)(wb + (size_t)c * COUT + o4 * 4);
        }
        __syncthreads();
#pragma unroll
        for (int k = 0; k < CIN; k++) {
            float4 a4 = *(const float4*)&As[k][ty * 4];
            float4 b4 = *(const float4*)&Bs[k][tx * 4];
            float a[4] = {a4.x, a4.y, a4.z, a4.w};
            float b[4] = {b4.x, b4.y, b4.z, b4.w};
#pragma unroll
            for (int i = 0; i < 4; i++)
#pragma unroll
                for (int j = 0; j < 4; j++)
                    acc[i][j] = fmaf(a[i], b[j], acc[i][j]);
        }
    }

#pragma unroll
    for (int i = 0; i < 4; i++) {
        int b = b0 + ty * 4 + i;
        float v0 = fmaxf(acc[i][0] + shift[o0 + tx * 4 + 0], 0.f);
        float v1 = fmaxf(acc[i][1] + shift[o0 + tx * 4 + 1], 0.f);
        float v2 = fmaxf(acc[i][2] + shift[o0 + tx * 4 + 2], 0.f);
        float v3 = fmaxf(acc[i][3] + shift[o0 + tx * 4 + 3], 0.f);
        if (WHICH == 2) {
            __half* op = g_m2 + ((size_t)b * POS + pos) * COUT + o0 + tx * 4;
            __half2 h0 = __floats2half2_rn(v0, v1);
            __half2 h1 = __floats2half2_rn(v2, v3);
            *(__half2*)op = h0;
            *(__half2*)(op + 2) = h1;
        } else {
            float* op = g_m3 + ((size_t)b * POS + pos) * COUT + o0 + tx * 4;
            *(float4*)op = make_float4(v0, v1, v2, v3);
        }
    }
}

// ================= gate =================
__global__ void gate_kernel(const float* __restrict__ fc_w, const float* __restrict__ fc_b) {
    int b = blockIdx.x, t = threadIdx.x;
    __shared__ float pooled[128];
    __shared__ float logit[4];
    const float* p = g_m3 + (size_t)b * 4096 + t;
    float s = 0.f;
#pragma unroll
    for (int i = 0; i < 32; i++) s += p[i * 128];
    pooled[t] = s * (1.0f / 32.0f);
    __syncthreads();
    if (t < 4) {
        float l = fc_b[t];
        const float* wrow = fc_w + t * 128;
        for (int c = 0; c < 128; c++) l = fmaf(pooled[c], wrow[c], l);
        logit[t] = l;
    }
    __syncthreads();
    if (t == 0) {
        float mx = fmaxf(fmaxf(logit[0], logit[1]), fmaxf(logit[2], logit[3]));
        float e0 = expf(logit[0] - mx), e1 = expf(logit[1] - mx);
        float e2 = expf(logit[2] - mx), e3 = expf(logit[3] - mx);
        float inv = 1.f / (e0 + e1 + e2 + e3);
        g_gw[b * 4 + 0] = e0 * inv;
        g_gw[b * 4 + 1] = e1 * inv;
        g_gw[b * 4 + 2] = e2 * inv;
        g_gw[b * 4 + 3] = e3 * inv;
    }
}

// ================= mma.sync GEMM, 1-pass fp16, 2-stage kT=32 =================
// MODE 1: GEGLU xh x W1h -> hid (fp16, UNscaled)
// MODE 2: per-expert out GEMM hid_h x W2h, split-K x4 (z = e*4+ks)
#define TILE_B   10240    // 128 rows * 80B
#define STAGE_B  20480    // 2 tiles: A, B
#define SMEM_BYTES 40960

template<int MODE>
__global__ void __launch_bounds__(256, 2) mma_gemm_kernel(const float* __restrict__ b1) {
    extern __shared__ char smem[];
    unsigned sb = smem_u32(smem);
    int t = threadIdx.x, wid = t >> 5, lid = t & 31;

    constexpr int KT = 40;

    int m0 = blockIdx.x * 128;
    int e = 0, h0 = 0, n0 = 0, z = 0;
    size_t kbase = 0;
    if (MODE == 1) { e = blockIdx.y / 80; h0 = (blockIdx.y % 80) * 64; }
    else {
        n0 = blockIdx.y * 128;
        z = blockIdx.z;
        kbase = (size_t)(z >> 2) * 5120 + (size_t)(z & 3) * 1280;
    }

    const __half* gsrc[4];
    unsigned sdst[4];
#pragma unroll
    for (int i = 0; i < 4; i++) {
        int c = t + 256 * i;
        int tile = c >> 9, rs = c & 511, row = rs >> 2, seg = rs & 3;
        const __half* base;
        size_t grow;
        if (MODE == 1) {
            if (tile == 0) {
                base = g_xh;
                grow = (size_t)(m0 + row) * 1280;
            } else {
                int g = e * 10240 + (row & 1) * 5120 + h0 + (row >> 1);
                base = g_w1h;
                grow = (size_t)g * 1280;
            }
        } else {
            if (tile == 0) {
                base = g_hh;
                grow = (size_t)(m0 + row) * 20480;
            } else {
                base = g_w2h;
                grow = (size_t)(n0 + row) * 20480;
            }
        }
        gsrc[i] = base + grow + seg * 8;
        sdst[i] = sb + tile * TILE_B + row * 80 + seg * 16;
    }

#pragma unroll
    for (int st = 0; st < 2; st++) {
        size_t k0 = kbase + st * 32;
#pragma unroll
        for (int i = 0; i < 4; i++) CP_ASYNC16(sdst[i] + st * STAGE_B, gsrc[i] + k0);
        CP_COMMIT();
    }

    float cacc[2][8][4];
#pragma unroll
    for (int mf = 0; mf < 2; mf++)
#pragma unroll
        for (int nf = 0; nf < 8; nf++)
#pragma unroll
            for (int q = 0; q < 4; q++) cacc[mf][nf][q] = 0.f;

    unsigned warpM = (wid & 3) * 32;
    unsigned warpN = (wid >> 2) * 64;

    for (int kt = 0; kt < KT; kt++) {
        CP_WAIT1();
        __syncthreads();
        int st = kt & 1;
        unsigned sA = sb + st * STAGE_B;
        unsigned sB = sA + TILE_B;

#pragma unroll
        for (int ks = 0; ks < 2; ks++) {
            unsigned aH[2][4];
#pragma unroll
            for (int mf = 0; mf < 2; mf++) {
                unsigned off = (warpM + mf * 16 + (lid & 15)) * 80 + ks * 32 + (lid >> 4) * 16;
                ldsm4(aH[mf], sA + off);
            }
#pragma unroll
            for (int nf2 = 0; nf2 < 4; nf2++) {
                unsigned off = (warpN + nf2 * 16 + (lid & 7) + ((lid >> 4) & 1) * 8) * 80 +
                               ks * 32 + ((lid >> 3) & 1) * 16;
                unsigned rH[4];
                ldsm4(rH, sB + off);
#pragma unroll
                for (int mf = 0; mf < 2; mf++) {
                    MMA16816(cacc[mf][2 * nf2],     aH[mf], rH[0], rH[1]);
                    MMA16816(cacc[mf][2 * nf2 + 1], aH[mf], rH[2], rH[3]);
                }
            }
        }
        __syncthreads();
        int ktn = kt + 2;
        if (ktn < KT) {
            size_t k0 = kbase + (size_t)ktn * 32;
#pragma unroll
            for (int i = 0; i < 4; i++) CP_ASYNC16(sdst[i] + st * STAGE_B, gsrc[i] + k0);
        }
        CP_COMMIT();
    }

    int grp = lid >> 2, qd = lid & 3;
    if (MODE == 1) {
        const float* bv = b1 + (size_t)e * 10240;
#pragma unroll
        for (int mf = 0; mf < 2; mf++) {
#pragma unroll
            for (int half = 0; half < 2; half++) {
                int n = m0 + warpM + mf * 16 + grp + half * 8;
                size_t ob = (size_t)n * 20480 + (size_t)e * 5120;
#pragma unroll
                for (int nf = 0; nf < 8; nf++) {
                    int h = h0 + (warpN >> 1) + nf * 4 + qd;
                    float val  = cacc[mf][nf][half * 2 + 0];
                    float gate = cacc[mf][nf][half * 2 + 1];
                    float v = val + bv[h];
                    float g = gate + bv[5120 + h];
                    float hid = v * (0.5f * g * (1.f + erff(g * 0.70710678118654752f)));
                    g_hh[ob + h] = __float2half_rn(hid);
                }
            }
        }
    } else {
        size_t zb = (size_t)z * 1310720;
#pragma unroll
        for (int mf = 0; mf < 2; mf++) {
#pragma unroll
            for (int half = 0; half < 2; half++) {
                int n = m0 + warpM + mf * 16 + grp + half * 8;
                size_t rb = zb + (size_t)n * 1280;
#pragma unroll
                for (int nf = 0; nf < 8; nf++) {
                    int col = n0 + warpN + nf * 8 + qd * 2;
                    g_part[rb + col]     = cacc[mf][nf][half * 2 + 0];
                    g_part[rb + col + 1] = cacc[mf][nf][half * 2 + 1];
                }
            }
        }
    }
}

// ================= reduce: sum splits, gate-weight experts, add bias =================
__global__ void reduce_kernel(const float* __restrict__ b2, float* __restrict__ out) {
    int i = blockIdx.x * 256 + threadIdx.x;
    int n = i / 1280, j = i - n * 1280;
    const float* gw = g_gw + n * 4;
    float s = 0.f;
#pragma unroll
    for (int e = 0; e < 4; e++) {
        size_t base = (size_t)e * 4 * 1310720 + i;
        float p = g_part[base] + g_part[base + 1310720] +
                  g_part[base + 2621440] + g_part[base + 3932160];
        s += gw[e] * (p + b2[e * 1280 + j]);
    }
    out[i] = s;
}

// ================= launch =================
extern "C" void kernel_launch(void* const* d_in, const int* in_sizes, int n_in,
                              void* d_out, int out_size) {
    const float* x    = (const float*)d_in[0];
    const float* mask = (const float*)d_in[1];
    const float* c1w  = (const float*)d_in[2];
    const float* c1b  = (const float*)d_in[3];
    const float* bn1g = (const float*)d_in[4];
    const float* bn1b = (const float*)d_in[5];
    const float* bn1m = (const float*)d_in[6];
    const float* bn1v = (const float*)d_in[7];
    const float* c2w  = (const float*)d_in[8];
    const float* c2b  = (const float*)d_in[9];
    const float* bn2g = (const float*)d_in[10];
    const float* bn2b = (const float*)d_in[11];
    const float* bn2m = (const float*)d_in[12];
    const float* bn2v = (const float*)d_in[13];
    const float* c3w  = (const float*)d_in[14];
    const float* c3b  = (const float*)d_in[15];
    const float* bn3g = (const float*)d_in[16];
    const float* bn3b = (const float*)d_in[17];
    const float* bn3m = (const float*)d_in[18];
    const float* bn3v = (const float*)d_in[19];
    const float* fcw  = (const float*)d_in[20];
    const float* fcb  = (const float*)d_in[21];
    const float* w1   = (const float*)d_in[22];
    const float* b1   = (const float*)d_in[23];
    const float* w2   = (const float*)d_in[24];
    const float* b2   = (const float*)d_in[25];
    float* out = (float*)d_out;

    cudaFuncSetAttribute(mma_gemm_kernel<1>, cudaFuncAttributeMaxDynamicSharedMemorySize, SMEM_BYTES);
    cudaFuncSetAttribute(mma_gemm_kernel<2>, cudaFuncAttributeMaxDynamicSharedMemorySize, SMEM_BYTES);

    prep_kernel<2><<<216, 256>>>(c2w, c2b, bn2g, bn2b, bn2m, bn2v);
    prep_kernel<3><<<864, 256>>>(c3w, c3b, bn3g, bn3b, bn3m, bn3v);
    cvt_x_kernel<<<5120, 256>>>(x);
    trans_w1_kernel<<<dim3(320, 40, 4), dim3(32, 8)>>>(w1);
    trans_w2_kernel<<<dim3(40, 160, 4), dim3(32, 8)>>>(w2);
    conv1_kernel<<<dim3(1024, 8), 256>>>(mask, c1w, c1b, bn1g, bn1b, bn1m, bn1v);
    conv_gemm_kernel<2><<<dim3(256, 16, 1), 256>>>();
    conv_gemm_kernel<3><<<dim3(32, 16, 2), 256>>>();
    gate_kernel<<<1024, 128>>>(fcw, fcb);
    mma_gemm_kernel<1><<<dim3(8, 320), 256, SMEM_BYTES>>>(b1);
    mma_gemm_kernel<2><<<dim3(8, 10, 16), 256, SMEM_BYTES>>>(b1);
    reduce_kernel<<<5120, 256>>>(b2, out);
}

// round 16
// speedup vs baseline: 3.0623x; 1.8075x over previous
#include <cuda_runtime.h>
#include <cuda_fp16.h>
#include <math.h>

#define BN_EPS 1e-5f

// ================= scratch =================
__device__ __half g_m1[67108864]; // conv1 out, channels-last fp16 [1024][2048][32]
__device__ __half g_m2[16777216]; // conv2 out, channels-last fp16 [1024][256][64]
__device__ float g_m3[4194304];   // conv3 out, channels-last fp32 [1024][32][128]
__device__ __half g_cw2[55296];   // conv2 w fp16 [tap27][o64][c32]
__device__ float g_shift2[64];
__device__ __half g_cw3[221184];  // conv3 w fp16 [tap27][o128][c64]
__device__ float g_shift3[128];
__device__ float g_gw[4096];      // [1024][4]
// fp16 operands, all singly quantized (x, W1, W2, hid)
__device__ __half g_xh[1310720];                  // x [1024][1280]
__device__ __half g_w1h[52428800];                // W1^T [40960][1280]
__device__ __half g_w2h[26214400];                // W2^T [1280][20480]
__device__ __half g_hh[20971520];                 // hid [1024][20480] (UNscaled)
__device__ float g_part[20971520]; // [16 = e*4+ksplit][1024][1280] partials

// ================= helpers =================
__device__ __forceinline__ unsigned smem_u32(const void* ptr) {
    unsigned a;
    asm("{ .reg .u64 t; cvta.to.shared.u64 t, %1; cvt.u32.u64 %0, t; }" : "=r"(a) : "l"(ptr));
    return a;
}
#define CP_ASYNC16(dst, src) \
    asm volatile("cp.async.cg.shared.global [%0], [%1], 16;" :: "r"(dst), "l"(src))
#define CP_COMMIT() asm volatile("cp.async.commit_group;" ::: "memory")
#define CP_WAIT1()  asm volatile("cp.async.wait_group 1;" ::: "memory")

__device__ __forceinline__ void ldsm4(unsigned* r, unsigned addr) {
    asm volatile("ldmatrix.sync.aligned.m8n8.x4.shared.b16 {%0,%1,%2,%3}, [%4];"
                 : "=r"(r[0]), "=r"(r[1]), "=r"(r[2]), "=r"(r[3]) : "r"(addr));
}
#define MMA16816(c, a, b0v, b1v) \
    asm volatile("mma.sync.aligned.m16n8k16.row.col.f32.f16.f16.f32 " \
        "{%0,%1,%2,%3}, {%4,%5,%6,%7}, {%8,%9}, {%0,%1,%2,%3};" \
        : "+f"((c)[0]), "+f"((c)[1]), "+f"((c)[2]), "+f"((c)[3]) \
        : "r"((a)[0]), "r"((a)[1]), "r"((a)[2]), "r"((a)[3]), "r"(b0v), "r"(b1v))

// ================= prep: conv weights + BN fold -> fp16 [tap][o][c] =================
template<int WHICH>
__global__ void prep_kernel(const float* __restrict__ w, const float* __restrict__ bias,
                            const float* __restrict__ bng, const float* __restrict__ bnb,
                            const float* __restrict__ bnm, const float* __restrict__ bnv) {
    constexpr int CIN  = (WHICH == 2) ? 32 : 64;
    constexpr int COUT = (WHICH == 2) ? 64 : 128;
    __half* cw   = (WHICH == 2) ? g_cw2 : g_cw3;
    float* shift = (WHICH == 2) ? g_shift2 : g_shift3;
    int idx = blockIdx.x * 256 + threadIdx.x;
    const int total = CIN * 27 * COUT;
    if (idx < total) {
        int c = idx % CIN;
        int o = (idx / CIN) % COUT;
        int tap = idx / (CIN * COUT);
        float s = rsqrtf(bnv[o] + BN_EPS) * bng[o];
        cw[idx] = __float2half_rn(w[((size_t)o * CIN + c) * 27 + tap] * s);
    }
    if (idx < COUT) {
        float s = rsqrtf(bnv[idx] + BN_EPS) * bng[idx];
        shift[idx] = (bias[idx] - bnm[idx]) * s + bnb[idx];
    }
}

// ================= fp16 conversion =================
__global__ void cvt_x_kernel(const float* __restrict__ x) {
    int i = blockIdx.x * 256 + threadIdx.x;
    if (i < 1310720) g_xh[i] = __float2half_rn(x[i]);
}

__global__ void trans_w1_kernel(const float* __restrict__ w1) {
    __shared__ float tile[32][33];
    int e = blockIdx.z;
    int j0 = blockIdx.x * 32, d0 = blockIdx.y * 32;
    const float* W = w1 + (size_t)e * 13107200;
    int tx = threadIdx.x, ty = threadIdx.y;
#pragma unroll
    for (int r = 0; r < 32; r += 8)
        tile[ty + r][tx] = W[(size_t)(d0 + ty + r) * 10240 + j0 + tx];
    __syncthreads();
#pragma unroll
    for (int r = 0; r < 32; r += 8) {
        size_t o = (size_t)(e * 10240 + j0 + ty + r) * 1280 + d0 + tx;
        g_w1h[o] = __float2half_rn(tile[tx][ty + r]);
    }
}

__global__ void trans_w2_kernel(const float* __restrict__ w2) {
    __shared__ float tile[32][33];
    int e = blockIdx.z;
    int j0 = blockIdx.x * 32, i0 = blockIdx.y * 32;
    const float* W = w2 + (size_t)e * 6553600;
    int tx = threadIdx.x, ty = threadIdx.y;
#pragma unroll
    for (int r = 0; r < 32; r += 8)
        tile[ty + r][tx] = W[(size_t)(i0 + ty + r) * 1280 + j0 + tx];
    __syncthreads();
#pragma unroll
    for (int r = 0; r < 32; r += 8) {
        size_t o = (size_t)(j0 + ty + r) * 20480 + e * 5120 + i0 + tx;
        g_w2h[o] = __float2half_rn(tile[tx][ty + r]);
    }
}

// ================= conv1: channels-last fp16 output =================
__global__ void conv1_kernel(const float* __restrict__ mask,
                             const float* __restrict__ w, const float* __restrict__ bias,
                             const float* __restrict__ bng, const float* __restrict__ bnb,
                             const float* __restrict__ bnm, const float* __restrict__ bnv) {
    __shared__ float ws[32][27];
    __shared__ float sscale[32], sshift[32];
    int t = threadIdx.x;
    if (t < 32) {
        float s = rsqrtf(bnv[t] + BN_EPS) * bng[t];
        sscale[t] = s;
        sshift[t] = (bias[t] - bnm[t]) * s + bnb[t];
    }
    __syncthreads();
    for (int idx = t; idx < 864; idx += 256) {
        int o = idx / 27, tap = idx % 27;
        ws[o][tap] = w[idx] * sscale[o];
    }
    __syncthreads();

    int b = blockIdx.x, d = blockIdx.y;
    int h = t >> 4, wq = t & 15;
    const float* mb = mask + (size_t)b * 16384;

    float v[27];
#pragma unroll
    for (int kd = 0; kd < 3; kd++)
#pragma unroll
        for (int kh = 0; kh < 3; kh++)
#pragma unroll
            for (int kw = 0; kw < 3; kw++) {
                int zd = 2 * d - 1 + kd, zh = 2 * h - 1 + kh, zw = 2 * wq - 1 + kw;
                bool ok = (unsigned)zd < 16u && (unsigned)zh < 32u && (unsigned)zw < 32u;
                v[(kd * 3 + kh) * 3 + kw] = ok ? mb[zd * 1024 + zh * 32 + zw] : 0.f;
            }

    __half2 o16[16];
#pragma unroll
    for (int o = 0; o < 16; o++) {
        float a0 = 0.f, a1 = 0.f;
#pragma unroll
        for (int tap = 0; tap < 27; tap++) {
            a0 = fmaf(ws[2 * o][tap], v[tap], a0);
            a1 = fmaf(ws[2 * o + 1][tap], v[tap], a1);
        }
        o16[o] = __floats2half2_rn(fmaxf(a0 + sshift[2 * o], 0.f),
                                   fmaxf(a1 + sshift[2 * o + 1], 0.f));
    }
    __half* op = g_m1 + ((((size_t)b * 8 + d) * 256) + t) * 32;
#pragma unroll
    for (int q = 0; q < 4; q++)
        *(uint4*)(op + q * 8) = ((uint4*)o16)[q];
}

// ================= conv2/3: fp16 tensor-core implicit GEMM =================
// per position: out[64 batch, COUT] += gathered_in[64, CIN] x w[tap][COUT, CIN]^T
template<int WHICH>
__global__ void conv_mma_kernel() {
    constexpr int CIN  = (WHICH == 2) ? 32 : 64;
    constexpr int COUT = (WHICH == 2) ? 64 : 128;
    constexpr int DIN  = (WHICH == 2) ? 8 : 4;
    constexpr int HIN  = (WHICH == 2) ? 16 : 8;
    constexpr int WIN  = (WHICH == 2) ? 16 : 8;
    constexpr int HOUT = (WHICH == 2) ? 8 : 4;
    constexpr int WOUT = (WHICH == 2) ? 8 : 4;
    constexpr int DHW  = DIN * HIN * WIN;
    constexpr int POS  = ((WHICH == 2) ? 4 : 2) * HOUT * WOUT;
    constexpr int THREADS = (WHICH == 2) ? 128 : 256;
    constexpr int PITCH  = CIN * 2 + 16;   // 80 / 144 (ldmatrix conflict-free)
    constexpr int KSTEPS = CIN / 16;       // 2 / 4
    constexpr int ACH    = CIN / 8;        // 16B chunks per row: 4 / 8

    const __half* in   = (WHICH == 2) ? g_m1 : g_m2;
    const __half* cw   = (WHICH == 2) ? g_cw2 : g_cw3;
    const float* shift = (WHICH == 2) ? g_shift2 : g_shift3;

    __shared__ __align__(16) char As[64 * PITCH];
    __shared__ __align__(16) char Bs[COUT * PITCH];
    __shared__ int offs[27];

    int pos = blockIdx.x;
    int t = threadIdx.x;
    int wid = t >> 5, lid = t & 31;
    if (t < 27) {
        int d = pos / (HOUT * WOUT);
        int rem = pos % (HOUT * WOUT);
        int h = rem / WOUT, w = rem % WOUT;
        int kd = t / 9, r = t % 9, kh = r / 3, kw = r % 3;
        int zd = 2 * d - 1 + kd, zh = 2 * h - 1 + kh, zw = 2 * w - 1 + kw;
        bool ok = (unsigned)zd < (unsigned)DIN && (unsigned)zh < (unsigned)HIN &&
                  (unsigned)zw < (unsigned)WIN;
        offs[t] = ok ? ((zd * HIN + zh) * WIN + zw) : -1;
    }
    __syncthreads();

    int b0 = blockIdx.y * 64;
    unsigned sA = smem_u32(As), sB = smem_u32(Bs);
    unsigned warpM = (wid & 1) * 32;
    unsigned warpN = (wid >> 1) * 32;

    float cacc[2][4][4];
#pragma unroll
    for (int mf = 0; mf < 2; mf++)
#pragma unroll
        for (int nf = 0; nf < 4; nf++)
#pragma unroll
            for (int q = 0; q < 4; q++) cacc[mf][nf][q] = 0.f;

    for (int tap = 0; tap < 27; tap++) {
        int off = offs[tap];
        if (off < 0) continue;
        __syncthreads();
        // A gather: 64 rows x CIN ch (16B chunks)
#pragma unroll
        for (int i = 0; i < (64 * ACH) / THREADS; i++) {
            int c = t + THREADS * i;
            int row = c / ACH, seg = c % ACH;
            *(uint4*)(As + row * PITCH + seg * 16) =
                *(const uint4*)(in + (size_t)(b0 + row) * (DHW * CIN) +
                                (size_t)off * CIN + seg * 8);
        }
        // B: COUT rows x CIN ch
        const __half* wb = cw + (size_t)tap * COUT * CIN;
#pragma unroll
        for (int i = 0; i < (COUT * ACH) / THREADS; i++) {
            int c = t + THREADS * i;
            int o = c / ACH, seg = c % ACH;
            *(uint4*)(Bs + o * PITCH + seg * 16) = *(const uint4*)(wb + o * CIN + seg * 8);
        }
        __syncthreads();
#pragma unroll
        for (int ks = 0; ks < KSTEPS; ks++) {
            unsigned a[2][4];
#pragma unroll
            for (int mf = 0; mf < 2; mf++) {
                unsigned ao = (warpM + mf * 16 + (lid & 15)) * PITCH + ks * 32 + (lid >> 4) * 16;
                ldsm4(a[mf], sA + ao);
            }
#pragma unroll
            for (int nf2 = 0; nf2 < 2; nf2++) {
                unsigned bo = (warpN + nf2 * 16 + (lid & 7) + ((lid >> 4) & 1) * 8) * PITCH +
                              ks * 32 + ((lid >> 3) & 1) * 16;
                unsigned r[4];
                ldsm4(r, sB + bo);
#pragma unroll
                for (int mf = 0; mf < 2; mf++) {
                    MMA16816(cacc[mf][2 * nf2],     a[mf], r[0], r[1]);
                    MMA16816(cacc[mf][2 * nf2 + 1], a[mf], r[2], r[3]);
                }
            }
        }
    }

    // epilogue: shift + relu, write channels-last
    int grp = lid >> 2, qd = lid & 3;
#pragma unroll
    for (int mf = 0; mf < 2; mf++) {
#pragma unroll
        for (int half = 0; half < 2; half++) {
            int b = b0 + (int)warpM + mf * 16 + grp + half * 8;
#pragma unroll
            for (int nf = 0; nf < 4; nf++) {
                int o = (int)warpN + nf * 8 + qd * 2;
                float v0 = fmaxf(cacc[mf][nf][half * 2 + 0] + shift[o], 0.f);
                float v1 = fmaxf(cacc[mf][nf][half * 2 + 1] + shift[o + 1], 0.f);
                if (WHICH == 2) {
                    __half* op = g_m2 + ((size_t)b * POS + pos) * COUT + o;
                    *(__half2*)op = __floats2half2_rn(v0, v1);
                } else {
                    float* op = g_m3 + ((size_t)b * POS + pos) * COUT + o;
                    *(float2*)op = make_float2(v0, v1);
                }
            }
        }
    }
}

// ================= gate =================
__global__ void gate_kernel(const float* __restrict__ fc_w, const float* __restrict__ fc_b) {
    int b = blockIdx.x, t = threadIdx.x;
    __shared__ float pooled[128];
    __shared__ float logit[4];
    const float* p = g_m3 + (size_t)b * 4096 + t;
    float s = 0.f;
#pragma unroll
    for (int i = 0; i < 32; i++) s += p[i * 128];
    pooled[t] = s * (1.0f / 32.0f);
    __syncthreads();
    if (t < 4) {
        float l = fc_b[t];
        const float* wrow = fc_w + t * 128;
        for (int c = 0; c < 128; c++) l = fmaf(pooled[c], wrow[c], l);
        logit[t] = l;
    }
    __syncthreads();
    if (t == 0) {
        float mx = fmaxf(fmaxf(logit[0], logit[1]), fmaxf(logit[2], logit[3]));
        float e0 = expf(logit[0] - mx), e1 = expf(logit[1] - mx);
        float e2 = expf(logit[2] - mx), e3 = expf(logit[3] - mx);
        float inv = 1.f / (e0 + e1 + e2 + e3);
        g_gw[b * 4 + 0] = e0 * inv;
        g_gw[b * 4 + 1] = e1 * inv;
        g_gw[b * 4 + 2] = e2 * inv;
        g_gw[b * 4 + 3] = e3 * inv;
    }
}

// ================= mma.sync GEMM, 1-pass fp16, 2-stage kT=32 =================
// MODE 1: GEGLU xh x W1h -> hid (fp16, UNscaled)
// MODE 2: per-expert out GEMM hid_h x W2h, split-K x4 (z = e*4+ks)
#define TILE_B   10240    // 128 rows * 80B
#define STAGE_B  20480    // 2 tiles: A, B
#define SMEM_BYTES 40960

template<int MODE>
__global__ void __launch_bounds__(256, 2) mma_gemm_kernel(const float* __restrict__ b1) {
    extern __shared__ char smem[];
    unsigned sb = smem_u32(smem);
    int t = threadIdx.x, wid = t >> 5, lid = t & 31;

    constexpr int KT = 40;

    int m0 = blockIdx.x * 128;
    int e = 0, h0 = 0, n0 = 0, z = 0;
    size_t kbase = 0;
    if (MODE == 1) { e = blockIdx.y / 80; h0 = (blockIdx.y % 80) * 64; }
    else {
        n0 = blockIdx.y * 128;
        z = blockIdx.z;
        kbase = (size_t)(z >> 2) * 5120 + (size_t)(z & 3) * 1280;
    }

    const __half* gsrc[4];
    unsigned sdst[4];
#pragma unroll
    for (int i = 0; i < 4; i++) {
        int c = t + 256 * i;
        int tile = c >> 9, rs = c & 511, row = rs >> 2, seg = rs & 3;
        const __half* base;
        size_t grow;
        if (MODE == 1) {
            if (tile == 0) {
                base = g_xh;
                grow = (size_t)(m0 + row) * 1280;
            } else {
                int g = e * 10240 + (row & 1) * 5120 + h0 + (row >> 1);
                base = g_w1h;
                grow = (size_t)g * 1280;
            }
        } else {
            if (tile == 0) {
                base = g_hh;
                grow = (size_t)(m0 + row) * 20480;
            } else {
                base = g_w2h;
                grow = (size_t)(n0 + row) * 20480;
            }
        }
        gsrc[i] = base + grow + seg * 8;
        sdst[i] = sb + tile * TILE_B + row * 80 + seg * 16;
    }

#pragma unroll
    for (int st = 0; st < 2; st++) {
        size_t k0 = kbase + st * 32;
#pragma unroll
        for (int i = 0; i < 4; i++) CP_ASYNC16(sdst[i] + st * STAGE_B, gsrc[i] + k0);
        CP_COMMIT();
    }

    float cacc[2][8][4];
#pragma unroll
    for (int mf = 0; mf < 2; mf++)
#pragma unroll
        for (int nf = 0; nf < 8; nf++)
#pragma unroll
            for (int q = 0; q < 4; q++) cacc[mf][nf][q] = 0.f;

    unsigned warpM = (wid & 3) * 32;
    unsigned warpN = (wid >> 2) * 64;

    for (int kt = 0; kt < KT; kt++) {
        CP_WAIT1();
        __syncthreads();
        int st = kt & 1;
        unsigned sA = sb + st * STAGE_B;
        unsigned sB = sA + TILE_B;

#pragma unroll
        for (int ks = 0; ks < 2; ks++) {
            unsigned aH[2][4];
#pragma unroll
            for (int mf = 0; mf < 2; mf++) {
                unsigned off = (warpM + mf * 16 + (lid & 15)) * 80 + ks * 32 + (lid >> 4) * 16;
                ldsm4(aH[mf], sA + off);
            }
#pragma unroll
            for (int nf2 = 0; nf2 < 4; nf2++) {
                unsigned off = (warpN + nf2 * 16 + (lid & 7) + ((lid >> 4) & 1) * 8) * 80 +
                               ks * 32 + ((lid >> 3) & 1) * 16;
                unsigned rH[4];
                ldsm4(rH, sB + off);
#pragma unroll
                for (int mf = 0; mf < 2; mf++) {
                    MMA16816(cacc[mf][2 * nf2],     aH[mf], rH[0], rH[1]);
                    MMA16816(cacc[mf][2 * nf2 + 1], aH[mf], rH[2], rH[3]);
                }
            }
        }
        __syncthreads();
        int ktn = kt + 2;
        if (ktn < KT) {
            size_t k0 = kbase + (size_t)ktn * 32;
#pragma unroll
            for (int i = 0; i < 4; i++) CP_ASYNC16(sdst[i] + st * STAGE_B, gsrc[i] + k0);
        }
        CP_COMMIT();
    }

    int grp = lid >> 2, qd = lid & 3;
    if (MODE == 1) {
        const float* bv = b1 + (size_t)e * 10240;
#pragma unroll
        for (int mf = 0; mf < 2; mf++) {
#pragma unroll
            for (int half = 0; half < 2; half++) {
                int n = m0 + warpM + mf * 16 + grp + half * 8;
                size_t ob = (size_t)n * 20480 + (size_t)e * 5120;
#pragma unroll
                for (int nf = 0; nf < 8; nf++) {
                    int h = h0 + (warpN >> 1) + nf * 4 + qd;
                    float val  = cacc[mf][nf][half * 2 + 0];
                    float gate = cacc[mf][nf][half * 2 + 1];
                    float v = val + bv[h];
                    float g = gate + bv[5120 + h];
                    float hid = v * (0.5f * g * (1.f + erff(g * 0.70710678118654752f)));
                    g_hh[ob + h] = __float2half_rn(hid);
                }
            }
        }
    } else {
        size_t zb = (size_t)z * 1310720;
#pragma unroll
        for (int mf = 0; mf < 2; mf++) {
#pragma unroll
            for (int half = 0; half < 2; half++) {
                int n = m0 + warpM + mf * 16 + grp + half * 8;
                size_t rb = zb + (size_t)n * 1280;
#pragma unroll
                for (int nf = 0; nf < 8; nf++) {
                    int col = n0 + warpN + nf * 8 + qd * 2;
                    g_part[rb + col]     = cacc[mf][nf][half * 2 + 0];
                    g_part[rb + col + 1] = cacc[mf][nf][half * 2 + 1];
                }
            }
        }
    }
}

// ================= reduce: sum splits, gate-weight experts, add bias =================
__global__ void reduce_kernel(const float* __restrict__ b2, float* __restrict__ out) {
    int i = blockIdx.x * 256 + threadIdx.x;
    int n = i / 1280, j = i - n * 1280;
    const float* gw = g_gw + n * 4;
    float s = 0.f;
#pragma unroll
    for (int e = 0; e < 4; e++) {
        size_t base = (size_t)e * 4 * 1310720 + i;
        float p = g_part[base] + g_part[base + 1310720] +
                  g_part[base + 2621440] + g_part[base + 3932160];
        s += gw[e] * (p + b2[e * 1280 + j]);
    }
    out[i] = s;
}

// ================= launch =================
extern "C" void kernel_launch(void* const* d_in, const int* in_sizes, int n_in,
                              void* d_out, int out_size) {
    const float* x    = (const float*)d_in[0];
    const float* mask = (const float*)d_in[1];
    const float* c1w  = (const float*)d_in[2];
    const float* c1b  = (const float*)d_in[3];
    const float* bn1g = (const float*)d_in[4];
    const float* bn1b = (const float*)d_in[5];
    const float* bn1m = (const float*)d_in[6];
    const float* bn1v = (const float*)d_in[7];
    const float* c2w  = (const float*)d_in[8];
    const float* c2b  = (const float*)d_in[9];
    const float* bn2g = (const float*)d_in[10];
    const float* bn2b = (const float*)d_in[11];
    const float* bn2m = (const float*)d_in[12];
    const float* bn2v = (const float*)d_in[13];
    const float* c3w  = (const float*)d_in[14];
    const float* c3b  = (const float*)d_in[15];
    const float* bn3g = (const float*)d_in[16];
    const float* bn3b = (const float*)d_in[17];
    const float* bn3m = (const float*)d_in[18];
    const float* bn3v = (const float*)d_in[19];
    const float* fcw  = (const float*)d_in[20];
    const float* fcb  = (const float*)d_in[21];
    const float* w1   = (const float*)d_in[22];
    const float* b1   = (const float*)d_in[23];
    const float* w2   = (const float*)d_in[24];
    const float* b2   = (const float*)d_in[25];
    float* out = (float*)d_out;

    cudaFuncSetAttribute(mma_gemm_kernel<1>, cudaFuncAttributeMaxDynamicSharedMemorySize, SMEM_BYTES);
    cudaFuncSetAttribute(mma_gemm_kernel<2>, cudaFuncAttributeMaxDynamicSharedMemorySize, SMEM_BYTES);

    prep_kernel<2><<<216, 256>>>(c2w, c2b, bn2g, bn2b, bn2m, bn2v);
    prep_kernel<3><<<864, 256>>>(c3w, c3b, bn3g, bn3b, bn3m, bn3v);
    cvt_x_kernel<<<5120, 256>>>(x);
    trans_w1_kernel<<<dim3(320, 40, 4), dim3(32, 8)>>>(w1);
    trans_w2_kernel<<<dim3(40, 160, 4), dim3(32, 8)>>>(w2);
    conv1_kernel<<<dim3(1024, 8), 256>>>(mask, c1w, c1b, bn1g, bn1b, bn1m, bn1v);
    conv_mma_kernel<2><<<dim3(256, 16), 128>>>();
    conv_mma_kernel<3><<<dim3(32, 16), 256>>>();
    gate_kernel<<<1024, 128>>>(fcw, fcb);
    mma_gemm_kernel<1><<<dim3(8, 320), 256, SMEM_BYTES>>>(b1);
    mma_gemm_kernel<2><<<dim3(8, 10, 16), 256, SMEM_BYTES>>>(b1);
    reduce_kernel<<<5120, 256>>>(b2, out);
}